// round 1
// baseline (speedup 1.0000x reference)
#include <cuda_runtime.h>
#include <cuda_bf16.h>
#include <math.h>

#define B_  8
#define L_  1024
#define S_  512
#define C_  768
#define H_  8
#define D_  96
#define F_  3072
#define NTX (B_*L_)   // 8192 tokens in x stream
#define NTC (B_*S_)   // 4096 tokens in c stream

// ---------------- scratch (static device allocations; no cudaMalloc) ----------------
__device__ float g_XN[(size_t)NTX*C_];
__device__ float g_CN[(size_t)NTC*C_];
__device__ float g_Q [(size_t)NTX*C_];
__device__ float g_K [(size_t)NTX*C_];
__device__ float g_V [(size_t)NTX*C_];
__device__ float g_AO[(size_t)NTX*C_];
__device__ float g_X2[(size_t)NTX*C_];
__device__ float g_P [(size_t)B_*H_*L_*L_];   // scores (max: self-attn)
__device__ float g_H [(size_t)NTX*F_];        // ffn hidden

// ---------------- reductions ----------------
__device__ __forceinline__ float blockReduceSum(float v) {
    __shared__ float sh[32];
    __syncthreads();
    int lane = threadIdx.x & 31, wid = threadIdx.x >> 5;
    #pragma unroll
    for (int o = 16; o; o >>= 1) v += __shfl_down_sync(0xffffffffu, v, o);
    if (lane == 0) sh[wid] = v;
    __syncthreads();
    int nw = blockDim.x >> 5;
    v = (threadIdx.x < nw) ? sh[threadIdx.x] : 0.0f;
    if (wid == 0) {
        #pragma unroll
        for (int o = 16; o; o >>= 1) v += __shfl_down_sync(0xffffffffu, v, o);
        if (lane == 0) sh[0] = v;
    }
    __syncthreads();
    return sh[0];
}

__device__ __forceinline__ float blockReduceMax(float v) {
    __shared__ float sh[32];
    __syncthreads();
    int lane = threadIdx.x & 31, wid = threadIdx.x >> 5;
    #pragma unroll
    for (int o = 16; o; o >>= 1) v = fmaxf(v, __shfl_down_sync(0xffffffffu, v, o));
    if (lane == 0) sh[wid] = v;
    __syncthreads();
    int nw = blockDim.x >> 5;
    v = (threadIdx.x < nw) ? sh[threadIdx.x] : -3.4e38f;
    if (wid == 0) {
        #pragma unroll
        for (int o = 16; o; o >>= 1) v = fmaxf(v, __shfl_down_sync(0xffffffffu, v, o));
        if (lane == 0) sh[0] = v;
    }
    __syncthreads();
    return sh[0];
}

// ---------------- layernorm: one block per row ----------------
__global__ void ln_kernel(const float* __restrict__ X,
                          const float* __restrict__ g, const float* __restrict__ b,
                          float* __restrict__ Y) {
    const int row = blockIdx.x;
    const float* x = X + (size_t)row * C_;
    float s = 0.f, s2 = 0.f;
    for (int j = threadIdx.x; j < C_; j += blockDim.x) {
        float v = x[j];
        s += v; s2 += v * v;
    }
    s  = blockReduceSum(s);
    s2 = blockReduceSum(s2);
    const float mean = s * (1.0f / C_);
    const float var  = s2 * (1.0f / C_) - mean * mean;
    const float inv  = rsqrtf(var + 1e-5f);
    float* y = Y + (size_t)row * C_;
    for (int j = threadIdx.x; j < C_; j += blockDim.x)
        y[j] = (x[j] - mean) * inv * g[j] + b[j];
}

// ---------------- SGEMM 128x128x8, 8x8 per thread, fused epilogues ----------------
// EPI: 0 = store, 2 = bias+gelu(exact erf), 3 = bias+residual
template <int EPI>
__global__ __launch_bounds__(256)
void sgemm128(const float* __restrict__ A, const float* __restrict__ W,
              const float* __restrict__ bias, const float* __restrict__ R,
              float* __restrict__ Cc,
              int M, int N, int K, int lda, int ldb, int ldc) {
    __shared__ float As[8][128];
    __shared__ float Bs[8][128];
    const int tid = threadIdx.x;
    const int tr = tid >> 4, tc = tid & 15;      // 16x16 threads
    const int m0 = blockIdx.y * 128, n0 = blockIdx.x * 128;

    const int arow = tid >> 1;                    // 0..127
    const int acol = (tid & 1) * 4;               // 0 or 4
    const int brow = tid >> 5;                    // 0..7
    const int bcol = (tid & 31) * 4;              // 0..124

    const float* Ap = A + (size_t)(m0 + arow) * lda + acol;
    const float* Wp = W + (size_t)brow * ldb + n0 + bcol;

    float acc[8][8];
    #pragma unroll
    for (int i = 0; i < 8; i++)
        #pragma unroll
        for (int j = 0; j < 8; j++) acc[i][j] = 0.f;

    for (int k0 = 0; k0 < K; k0 += 8) {
        float4 av = *(const float4*)(Ap + k0);
        As[acol + 0][arow] = av.x;
        As[acol + 1][arow] = av.y;
        As[acol + 2][arow] = av.z;
        As[acol + 3][arow] = av.w;
        *(float4*)(&Bs[brow][bcol]) = *(const float4*)(Wp + (size_t)k0 * ldb);
        __syncthreads();
        #pragma unroll
        for (int k = 0; k < 8; k++) {
            float a[8], bb[8];
            #pragma unroll
            for (int i = 0; i < 8; i++) a[i]  = As[k][tr * 8 + i];
            #pragma unroll
            for (int j = 0; j < 8; j++) bb[j] = Bs[k][tc * 8 + j];
            #pragma unroll
            for (int i = 0; i < 8; i++)
                #pragma unroll
                for (int j = 0; j < 8; j++)
                    acc[i][j] = fmaf(a[i], bb[j], acc[i][j]);
        }
        __syncthreads();
    }

    #pragma unroll
    for (int i = 0; i < 8; i++) {
        const int m = m0 + tr * 8 + i;
        #pragma unroll
        for (int j = 0; j < 8; j++) {
            const int n = n0 + tc * 8 + j;
            float v = acc[i][j];
            if (EPI >= 2) v += bias[n];
            if (EPI == 2) v = 0.5f * v * (1.0f + erff(v * 0.70710678118654752f));
            if (EPI == 3) v += R[(size_t)m * ldc + n];
            Cc[(size_t)m * ldc + n] = v;
        }
    }
}

// ---------------- attention scores: P[bh,i,j] = scale * Q_bh[i,:] . K_bh[j,:] ----------------
// grid: (Lk/64, Lq/64, B*H), block 256
__global__ __launch_bounds__(256)
void scores_kernel(const float* __restrict__ Q, const float* __restrict__ K,
                   float* __restrict__ P, int Lq, int Lk, float scale) {
    const int bh = blockIdx.z, b = bh / H_, h = bh % H_;
    const float* Qb = Q + (size_t)b * Lq * C_ + h * D_;
    const float* Kb = K + (size_t)b * Lk * C_ + h * D_;
    float* Pb = P + (size_t)bh * Lq * Lk;
    const int i0 = blockIdx.y * 64, j0 = blockIdx.x * 64;

    __shared__ float Qs[64][20];   // 16 + 4 pad
    __shared__ float Ks[64][20];
    const int tid = threadIdx.x;
    const int tr = tid >> 4, tc = tid & 15;
    const int lr = tid >> 2, lc = (tid & 3) * 4;

    float acc[4][4];
    #pragma unroll
    for (int i = 0; i < 4; i++)
        #pragma unroll
        for (int j = 0; j < 4; j++) acc[i][j] = 0.f;

    for (int d0 = 0; d0 < D_; d0 += 16) {
        *(float4*)(&Qs[lr][lc]) = *(const float4*)(Qb + (size_t)(i0 + lr) * C_ + d0 + lc);
        *(float4*)(&Ks[lr][lc]) = *(const float4*)(Kb + (size_t)(j0 + lr) * C_ + d0 + lc);
        __syncthreads();
        #pragma unroll
        for (int d = 0; d < 16; d++) {
            float a[4], bb[4];
            #pragma unroll
            for (int i = 0; i < 4; i++) a[i]  = Qs[tr * 4 + i][d];
            #pragma unroll
            for (int j = 0; j < 4; j++) bb[j] = Ks[tc * 4 + j][d];
            #pragma unroll
            for (int i = 0; i < 4; i++)
                #pragma unroll
                for (int j = 0; j < 4; j++)
                    acc[i][j] = fmaf(a[i], bb[j], acc[i][j]);
        }
        __syncthreads();
    }
    #pragma unroll
    for (int i = 0; i < 4; i++)
        #pragma unroll
        for (int j = 0; j < 4; j++)
            Pb[(size_t)(i0 + tr * 4 + i) * Lk + j0 + tc * 4 + j] = acc[i][j] * scale;
}

// ---------------- masked softmax per row ----------------
// grid (Lq, B*H). self_mode: keys masked to el=eff*us; else keys masked to eff.
// Fully-masked query rows (i>=el) -> uniform 1/Lk (matches -FLT_MAX fill + softmax).
__global__ void softmax_kernel(float* __restrict__ P, const int* __restrict__ eff,
                               const int* __restrict__ usp, int Lq, int Lk, int self_mode) {
    const int bh = blockIdx.y, b = bh / H_, i = blockIdx.x;
    float* row = P + ((size_t)bh * Lq + i) * Lk;
    const int us = usp[0];
    const int el = eff[b] * us;
    const int jl = self_mode ? el : eff[b];

    if (i >= el) {
        const float u = 1.0f / (float)Lk;
        for (int j = threadIdx.x; j < Lk; j += blockDim.x) row[j] = u;
        return;
    }
    float m = -3.4e38f;
    for (int j = threadIdx.x; j < jl; j += blockDim.x) m = fmaxf(m, row[j]);
    m = blockReduceMax(m);
    float s = 0.f;
    for (int j = threadIdx.x; j < jl; j += blockDim.x) s += expf(row[j] - m);
    s = blockReduceSum(s);
    const float inv = 1.0f / s;
    for (int j = threadIdx.x; j < Lk; j += blockDim.x)
        row[j] = (j < jl) ? expf(row[j] - m) * inv : 0.0f;
}

// ---------------- attention output: O_bh = P_bh @ V_bh  (per head, d=96) ----------------
// grid (Lq/64, B*H), block 256. Output tile 64 x 96, kk-tiles of 32.
__global__ __launch_bounds__(256)
void attnout_kernel(const float* __restrict__ P, const float* __restrict__ V,
                    float* __restrict__ AO, int Lq, int Lk) {
    const int bh = blockIdx.y, b = bh / H_, h = bh % H_;
    const float* Pb = P + (size_t)bh * Lq * Lk;
    const float* Vb = V + (size_t)b * Lk * C_ + h * D_;
    float* Ob = AO + (size_t)b * Lq * C_ + h * D_;
    const int i0 = blockIdx.x * 64;

    __shared__ float Ps[64][36];   // 32 + 4 pad
    __shared__ float Vs[32][100];  // 96 + 4 pad
    const int tid = threadIdx.x;
    const int tr = tid >> 4, tc = tid & 15;   // rows tr*4.., cols tc*6..

    float acc[4][6];
    #pragma unroll
    for (int i = 0; i < 4; i++)
        #pragma unroll
        for (int j = 0; j < 6; j++) acc[i][j] = 0.f;

    for (int k0 = 0; k0 < Lk; k0 += 32) {
        // load P tile 64x32 = 512 float4
        for (int t = tid; t < 512; t += 256) {
            int r = t >> 3, cq = (t & 7) * 4;
            *(float4*)(&Ps[r][cq]) = *(const float4*)(Pb + (size_t)(i0 + r) * Lk + k0 + cq);
        }
        // load V tile 32x96 = 768 float4
        for (int t = tid; t < 768; t += 256) {
            int r = t / 24, cq = (t % 24) * 4;
            *(float4*)(&Vs[r][cq]) = *(const float4*)(Vb + (size_t)(k0 + r) * C_ + cq);
        }
        __syncthreads();
        #pragma unroll
        for (int k = 0; k < 32; k++) {
            float p[4], v[6];
            #pragma unroll
            for (int i = 0; i < 4; i++) p[i] = Ps[tr * 4 + i][k];
            #pragma unroll
            for (int j = 0; j < 6; j++) v[j] = Vs[k][tc * 6 + j];
            #pragma unroll
            for (int i = 0; i < 4; i++)
                #pragma unroll
                for (int j = 0; j < 6; j++)
                    acc[i][j] = fmaf(p[i], v[j], acc[i][j]);
        }
        __syncthreads();
    }
    #pragma unroll
    for (int i = 0; i < 4; i++)
        #pragma unroll
        for (int j = 0; j < 6; j++)
            Ob[(size_t)(i0 + tr * 4 + i) * C_ + tc * 6 + j] = acc[i][j];
}

// ---------------- host orchestration ----------------
static void gemm(const float* A, const float* W, const float* bias, const float* R,
                 float* C, int M, int N, int K, int lda, int ldb, int ldc, int epi) {
    dim3 grid(N / 128, M / 128), blk(256);
    switch (epi) {
        case 2:  sgemm128<2><<<grid, blk>>>(A, W, bias, R, C, M, N, K, lda, ldb, ldc); break;
        case 3:  sgemm128<3><<<grid, blk>>>(A, W, bias, R, C, M, N, K, lda, ldb, ldc); break;
        default: sgemm128<0><<<grid, blk>>>(A, W, bias, R, C, M, N, K, lda, ldb, ldc); break;
    }
}

extern "C" void kernel_launch(void* const* d_in, const int* in_sizes, int n_in,
                              void* d_out, int out_size) {
    const float* x    = (const float*)d_in[0];
    const float* c    = (const float*)d_in[1];
    const int*   eff  = (const int*)  d_in[2];
    const int*   usr  = (const int*)  d_in[3];
    const float* Wq1  = (const float*)d_in[4];
    const float* Wkv1 = (const float*)d_in[5];
    const float* Wo1  = (const float*)d_in[6];
    const float* bo1  = (const float*)d_in[7];
    const float* Wq2  = (const float*)d_in[8];
    const float* Wkv2 = (const float*)d_in[9];
    const float* Wo2  = (const float*)d_in[10];
    const float* bo2  = (const float*)d_in[11];
    const float* g1   = (const float*)d_in[12];
    const float* b1   = (const float*)d_in[13];
    const float* g2   = (const float*)d_in[14];
    const float* b2   = (const float*)d_in[15];
    const float* g4   = (const float*)d_in[16];
    const float* b4   = (const float*)d_in[17];
    const float* gc   = (const float*)d_in[18];
    const float* bc   = (const float*)d_in[19];
    const float* Wf1  = (const float*)d_in[20];
    const float* bf1  = (const float*)d_in[21];
    const float* Wf2  = (const float*)d_in[22];
    const float* bf2  = (const float*)d_in[23];
    float* out = (float*)d_out;

    float *XN, *CN, *Q, *K, *V, *AO, *X2, *P, *Hf;
    cudaGetSymbolAddress((void**)&XN, g_XN);
    cudaGetSymbolAddress((void**)&CN, g_CN);
    cudaGetSymbolAddress((void**)&Q,  g_Q);
    cudaGetSymbolAddress((void**)&K,  g_K);
    cudaGetSymbolAddress((void**)&V,  g_V);
    cudaGetSymbolAddress((void**)&AO, g_AO);
    cudaGetSymbolAddress((void**)&X2, g_X2);
    cudaGetSymbolAddress((void**)&P,  g_P);
    cudaGetSymbolAddress((void**)&Hf, g_H);

    const float scale = rsqrtf((float)D_);

    // ---- self-attention ----
    ln_kernel<<<NTX, 256>>>(x, g1, b1, XN);
    gemm(XN, Wq1,       nullptr, nullptr, Q, NTX, C_, C_, C_, C_,     C_, 0);
    gemm(XN, Wkv1,      nullptr, nullptr, K, NTX, C_, C_, C_, 2 * C_, C_, 0);
    gemm(XN, Wkv1 + C_, nullptr, nullptr, V, NTX, C_, C_, C_, 2 * C_, C_, 0);
    scores_kernel<<<dim3(L_ / 64, L_ / 64, B_ * H_), 256>>>(Q, K, P, L_, L_, scale);
    softmax_kernel<<<dim3(L_, B_ * H_), 256>>>(P, eff, usr, L_, L_, 1);
    attnout_kernel<<<dim3(L_ / 64, B_ * H_), 256>>>(P, V, AO, L_, L_);
    gemm(AO, Wo1, bo1, x, X2, NTX, C_, C_, C_, C_, C_, 3);

    // ---- cross-attention ----
    ln_kernel<<<NTX, 256>>>(X2, g2, b2, XN);
    ln_kernel<<<NTC, 256>>>(c,  gc, bc, CN);
    gemm(XN, Wq2,       nullptr, nullptr, Q, NTX, C_, C_, C_, C_,     C_, 0);
    gemm(CN, Wkv2,      nullptr, nullptr, K, NTC, C_, C_, C_, 2 * C_, C_, 0);
    gemm(CN, Wkv2 + C_, nullptr, nullptr, V, NTC, C_, C_, C_, 2 * C_, C_, 0);
    scores_kernel<<<dim3(S_ / 64, L_ / 64, B_ * H_), 256>>>(Q, K, P, L_, S_, scale);
    softmax_kernel<<<dim3(L_, B_ * H_), 256>>>(P, eff, usr, L_, S_, 0);
    attnout_kernel<<<dim3(L_ / 64, B_ * H_), 256>>>(P, V, AO, L_, S_);
    gemm(AO, Wo2, bo2, X2, X2, NTX, C_, C_, C_, C_, C_, 3);

    // ---- FFN ----
    ln_kernel<<<NTX, 256>>>(X2, g4, b4, XN);
    gemm(XN, Wf1, bf1, nullptr, Hf,  NTX, F_, C_, C_, F_, F_, 2);
    gemm(Hf, Wf2, bf2, X2,      out, NTX, C_, F_, F_, C_, C_, 3);
}

// round 2
// speedup vs baseline: 1.4860x; 1.4860x over previous
#include <cuda_runtime.h>
#include <cuda_bf16.h>
#include <math.h>

#define B_  8
#define L_  1024
#define S_  512
#define C_  768
#define H_  8
#define D_  96
#define F_  3072
#define NTX (B_*L_)
#define NTC (B_*S_)

// ---------------- scratch ----------------
__device__ float g_XN[(size_t)NTX*C_];
__device__ float g_CN[(size_t)NTC*C_];
__device__ float g_Q [(size_t)NTX*C_];
__device__ float g_K [(size_t)NTX*C_];
__device__ float g_V [(size_t)NTX*C_];
__device__ float g_AO[(size_t)NTX*C_];
__device__ float g_X2[(size_t)NTX*C_];
__device__ float g_P [(size_t)B_*H_*L_*L_];
__device__ float g_H [(size_t)NTX*F_];

// ---------------- reductions ----------------
__device__ __forceinline__ float blockReduceSum(float v) {
    __shared__ float sh[32];
    __syncthreads();
    int lane = threadIdx.x & 31, wid = threadIdx.x >> 5;
    #pragma unroll
    for (int o = 16; o; o >>= 1) v += __shfl_down_sync(0xffffffffu, v, o);
    if (lane == 0) sh[wid] = v;
    __syncthreads();
    int nw = blockDim.x >> 5;
    v = (threadIdx.x < nw) ? sh[threadIdx.x] : 0.0f;
    if (wid == 0) {
        #pragma unroll
        for (int o = 16; o; o >>= 1) v += __shfl_down_sync(0xffffffffu, v, o);
        if (lane == 0) sh[0] = v;
    }
    __syncthreads();
    return sh[0];
}

__device__ __forceinline__ float blockReduceMax(float v) {
    __shared__ float sh[32];
    __syncthreads();
    int lane = threadIdx.x & 31, wid = threadIdx.x >> 5;
    #pragma unroll
    for (int o = 16; o; o >>= 1) v = fmaxf(v, __shfl_down_sync(0xffffffffu, v, o));
    if (lane == 0) sh[wid] = v;
    __syncthreads();
    int nw = blockDim.x >> 5;
    v = (threadIdx.x < nw) ? sh[threadIdx.x] : -3.4e38f;
    if (wid == 0) {
        #pragma unroll
        for (int o = 16; o; o >>= 1) v = fmaxf(v, __shfl_down_sync(0xffffffffu, v, o));
        if (lane == 0) sh[0] = v;
    }
    __syncthreads();
    return sh[0];
}

// ---------------- layernorm ----------------
__global__ void ln_kernel(const float* __restrict__ X,
                          const float* __restrict__ g, const float* __restrict__ b,
                          float* __restrict__ Y) {
    const int row = blockIdx.x;
    const float* x = X + (size_t)row * C_;
    float s = 0.f, s2 = 0.f;
    for (int j = threadIdx.x; j < C_; j += blockDim.x) {
        float v = x[j];
        s += v; s2 += v * v;
    }
    s  = blockReduceSum(s);
    s2 = blockReduceSum(s2);
    const float mean = s * (1.0f / C_);
    const float var  = s2 * (1.0f / C_) - mean * mean;
    const float inv  = rsqrtf(var + 1e-5f);
    float* y = Y + (size_t)row * C_;
    for (int j = threadIdx.x; j < C_; j += blockDim.x)
        y[j] = (x[j] - mean) * inv * g[j] + b[j];
}

// ---------------- masked softmax ----------------
__global__ void softmax_kernel(float* __restrict__ P, const int* __restrict__ eff,
                               const int* __restrict__ usp, int Lq, int Lk, int self_mode) {
    const int bh = blockIdx.y, b = bh / H_, i = blockIdx.x;
    float* row = P + ((size_t)bh * Lq + i) * Lk;
    const int us = usp[0];
    const int el = eff[b] * us;
    const int jl = self_mode ? el : eff[b];

    if (i >= el) {
        const float u = 1.0f / (float)Lk;
        for (int j = threadIdx.x; j < Lk; j += blockDim.x) row[j] = u;
        return;
    }
    float m = -3.4e38f;
    for (int j = threadIdx.x; j < jl; j += blockDim.x) m = fmaxf(m, row[j]);
    m = blockReduceMax(m);
    float s = 0.f;
    for (int j = threadIdx.x; j < jl; j += blockDim.x) s += expf(row[j] - m);
    s = blockReduceSum(s);
    const float inv = 1.0f / s;
    for (int j = threadIdx.x; j < Lk; j += blockDim.x)
        row[j] = (j < jl) ? expf(row[j] - m) * inv : 0.0f;
}

// ---------------- tf32 tensor-core GEMM ----------------
// C[M,N] = A[M,K] @ B  (B row-major [K,N] if !TRANSB, else B is [N,K] and we use B^T)
// Tiles: 128x128x32, 8 warps, warp tile 64(m) x 32(n) via m16n8k8 tf32 mma.
// EPI: 0 store, 1 scale*acc, 2 bias+gelu, 3 bias+residual(R)
#define BM 128
#define BN 128
#define BKt 32
#define LDS_ 136   // BM + 8 pad: conflict-free fragment loads

__device__ __forceinline__ unsigned f2tf32(float x) {
    unsigned u;
    asm("cvt.rna.tf32.f32 %0, %1;" : "=r"(u) : "f"(x));
    return u;
}

template <int EPI, int TRANSB>
__global__ __launch_bounds__(256, 2)
void mma_gemm(const float* __restrict__ A, const float* __restrict__ Bm,
              const float* __restrict__ bias, const float* __restrict__ R,
              float* __restrict__ Cc, float scale,
              int M, int N, int K, int lda, int ldb, int ldc,
              long long aBS, long long aHS,
              long long bBS, long long bHS,
              long long cBS, long long cHS) {
    __shared__ float As[BKt][LDS_];
    __shared__ float Bs[BKt][LDS_];

    const int z = blockIdx.z, zb = z / H_, zh = z % H_;
    const float* Ab = A  + (size_t)zb * aBS + (size_t)zh * aHS;
    const float* Bb = Bm + (size_t)zb * bBS + (size_t)zh * bHS;
    float*       Cb = Cc + (size_t)zb * cBS + (size_t)zh * cHS;

    const int m0 = blockIdx.y * BM, n0 = blockIdx.x * BN;
    const int tid = threadIdx.x, lane = tid & 31, warp = tid >> 5;
    const int wm = (warp & 1) * 64;       // warp m-offset within block
    const int wn = (warp >> 1) * 32;      // warp n-offset
    const int g = lane >> 2, tg = lane & 3;

    float acc[4][4][4];
    #pragma unroll
    for (int mi = 0; mi < 4; mi++)
        #pragma unroll
        for (int ni = 0; ni < 4; ni++)
            #pragma unroll
            for (int r = 0; r < 4; r++) acc[mi][ni][r] = 0.f;

    for (int k0 = 0; k0 < K; k0 += BKt) {
        // ---- load A tile [BM x BKt], transposed into As[k][m], tf32-rounded ----
        #pragma unroll
        for (int i = 0; i < 4; i++) {
            int fid = tid + i * 256;          // 0..1023
            int m = fid & 127;
            int kq = (fid >> 7) * 4;
            float4 v = *(const float4*)(Ab + (size_t)(m0 + m) * lda + k0 + kq);
            As[kq + 0][m] = __uint_as_float(f2tf32(v.x));
            As[kq + 1][m] = __uint_as_float(f2tf32(v.y));
            As[kq + 2][m] = __uint_as_float(f2tf32(v.z));
            As[kq + 3][m] = __uint_as_float(f2tf32(v.w));
        }
        // ---- load B tile into Bs[k][n] ----
        if (TRANSB) {
            // B logical [K,N] = Bmat[n][k] (Bmat row-major [N,K])
            #pragma unroll
            for (int i = 0; i < 4; i++) {
                int fid = tid + i * 256;
                int n = fid & 127;
                int kq = (fid >> 7) * 4;
                float4 v = *(const float4*)(Bb + (size_t)(n0 + n) * ldb + k0 + kq);
                Bs[kq + 0][n] = __uint_as_float(f2tf32(v.x));
                Bs[kq + 1][n] = __uint_as_float(f2tf32(v.y));
                Bs[kq + 2][n] = __uint_as_float(f2tf32(v.z));
                Bs[kq + 3][n] = __uint_as_float(f2tf32(v.w));
            }
        } else {
            #pragma unroll
            for (int i = 0; i < 4; i++) {
                int fid = tid + i * 256;
                int k = fid >> 5;                 // 0..31
                int nq = (fid & 31) * 4;
                float4 v;
                if (n0 + nq + 3 < N)
                    v = *(const float4*)(Bb + (size_t)(k0 + k) * ldb + n0 + nq);
                else
                    v = make_float4(0.f, 0.f, 0.f, 0.f);
                Bs[k][nq + 0] = __uint_as_float(f2tf32(v.x));
                Bs[k][nq + 1] = __uint_as_float(f2tf32(v.y));
                Bs[k][nq + 2] = __uint_as_float(f2tf32(v.z));
                Bs[k][nq + 3] = __uint_as_float(f2tf32(v.w));
            }
        }
        __syncthreads();

        #pragma unroll
        for (int kk = 0; kk < BKt; kk += 8) {
            unsigned a[4][4], bfr[4][2];
            #pragma unroll
            for (int mi = 0; mi < 4; mi++) {
                int mb = wm + mi * 16;
                a[mi][0] = __float_as_uint(As[kk + tg    ][mb + g    ]);
                a[mi][1] = __float_as_uint(As[kk + tg    ][mb + g + 8]);
                a[mi][2] = __float_as_uint(As[kk + 4 + tg][mb + g    ]);
                a[mi][3] = __float_as_uint(As[kk + 4 + tg][mb + g + 8]);
            }
            #pragma unroll
            for (int ni = 0; ni < 4; ni++) {
                int nb = wn + ni * 8;
                bfr[ni][0] = __float_as_uint(Bs[kk + tg    ][nb + g]);
                bfr[ni][1] = __float_as_uint(Bs[kk + 4 + tg][nb + g]);
            }
            #pragma unroll
            for (int mi = 0; mi < 4; mi++)
                #pragma unroll
                for (int ni = 0; ni < 4; ni++) {
                    asm volatile(
                        "mma.sync.aligned.m16n8k8.row.col.f32.tf32.tf32.f32 "
                        "{%0,%1,%2,%3}, {%4,%5,%6,%7}, {%8,%9}, {%0,%1,%2,%3};"
                        : "+f"(acc[mi][ni][0]), "+f"(acc[mi][ni][1]),
                          "+f"(acc[mi][ni][2]), "+f"(acc[mi][ni][3])
                        : "r"(a[mi][0]), "r"(a[mi][1]), "r"(a[mi][2]), "r"(a[mi][3]),
                          "r"(bfr[ni][0]), "r"(bfr[ni][1]));
                }
        }
        __syncthreads();
    }

    // ---- epilogue ----
    #pragma unroll
    for (int mi = 0; mi < 4; mi++) {
        const int r0 = m0 + wm + mi * 16 + g;
        const int r1 = r0 + 8;
        #pragma unroll
        for (int ni = 0; ni < 4; ni++) {
            const int cc = n0 + wn + ni * 8 + 2 * tg;
            float v00 = acc[mi][ni][0], v01 = acc[mi][ni][1];
            float v10 = acc[mi][ni][2], v11 = acc[mi][ni][3];
            if (EPI == 1) { v00 *= scale; v01 *= scale; v10 *= scale; v11 *= scale; }
            if (EPI >= 2) {
                float bz0 = bias[cc], bz1 = bias[cc + 1];
                v00 += bz0; v01 += bz1; v10 += bz0; v11 += bz1;
            }
            if (EPI == 2) {
                v00 = 0.5f * v00 * (1.0f + erff(v00 * 0.70710678118654752f));
                v01 = 0.5f * v01 * (1.0f + erff(v01 * 0.70710678118654752f));
                v10 = 0.5f * v10 * (1.0f + erff(v10 * 0.70710678118654752f));
                v11 = 0.5f * v11 * (1.0f + erff(v11 * 0.70710678118654752f));
            }
            if (EPI == 3) {
                v00 += R[(size_t)r0 * ldc + cc];
                v01 += R[(size_t)r0 * ldc + cc + 1];
                v10 += R[(size_t)r1 * ldc + cc];
                v11 += R[(size_t)r1 * ldc + cc + 1];
            }
            if (cc < N) {
                Cb[(size_t)r0 * ldc + cc] = v00;
                Cb[(size_t)r1 * ldc + cc] = v10;
            }
            if (cc + 1 < N) {
                Cb[(size_t)r0 * ldc + cc + 1] = v01;
                Cb[(size_t)r1 * ldc + cc + 1] = v11;
            }
        }
    }
}

// ---------------- host-side launch helpers ----------------
struct GemmArgs {
    const float *A, *B, *bias, *R;
    float *C;
    float scale;
    int M, N, K, lda, ldb, ldc;
    long long aBS, aHS, bBS, bHS, cBS, cHS;
    int batches;
};

template <int EPI, int TRANSB>
static void launch_mma(const GemmArgs& a) {
    dim3 grid((a.N + BN - 1) / BN, a.M / BM, a.batches), blk(256);
    mma_gemm<EPI, TRANSB><<<grid, blk>>>(a.A, a.B, a.bias, a.R, a.C, a.scale,
                                         a.M, a.N, a.K, a.lda, a.ldb, a.ldc,
                                         a.aBS, a.aHS, a.bBS, a.bHS, a.cBS, a.cHS);
}

extern "C" void kernel_launch(void* const* d_in, const int* in_sizes, int n_in,
                              void* d_out, int out_size) {
    const float* x    = (const float*)d_in[0];
    const float* c    = (const float*)d_in[1];
    const int*   eff  = (const int*)  d_in[2];
    const int*   usr  = (const int*)  d_in[3];
    const float* Wq1  = (const float*)d_in[4];
    const float* Wkv1 = (const float*)d_in[5];
    const float* Wo1  = (const float*)d_in[6];
    const float* bo1  = (const float*)d_in[7];
    const float* Wq2  = (const float*)d_in[8];
    const float* Wkv2 = (const float*)d_in[9];
    const float* Wo2  = (const float*)d_in[10];
    const float* bo2  = (const float*)d_in[11];
    const float* g1   = (const float*)d_in[12];
    const float* b1   = (const float*)d_in[13];
    const float* g2   = (const float*)d_in[14];
    const float* b2   = (const float*)d_in[15];
    const float* g4   = (const float*)d_in[16];
    const float* b4   = (const float*)d_in[17];
    const float* gc   = (const float*)d_in[18];
    const float* bc   = (const float*)d_in[19];
    const float* Wf1  = (const float*)d_in[20];
    const float* bf1  = (const float*)d_in[21];
    const float* Wf2  = (const float*)d_in[22];
    const float* bf2  = (const float*)d_in[23];
    float* out = (float*)d_out;

    float *XN, *CN, *Q, *K, *V, *AO, *X2, *P, *Hf;
    cudaGetSymbolAddress((void**)&XN, g_XN);
    cudaGetSymbolAddress((void**)&CN, g_CN);
    cudaGetSymbolAddress((void**)&Q,  g_Q);
    cudaGetSymbolAddress((void**)&K,  g_K);
    cudaGetSymbolAddress((void**)&V,  g_V);
    cudaGetSymbolAddress((void**)&AO, g_AO);
    cudaGetSymbolAddress((void**)&X2, g_X2);
    cudaGetSymbolAddress((void**)&P,  g_P);
    cudaGetSymbolAddress((void**)&Hf, g_H);

    const float scale = rsqrtf((float)D_);
    GemmArgs ga;

    // ---------- self-attention ----------
    ln_kernel<<<NTX, 256>>>(x, g1, b1, XN);

    ga = {XN, Wq1, nullptr, nullptr, Q, 1.f, NTX, C_, C_, C_, C_, C_, 0,0,0,0,0,0, 1};
    launch_mma<0,0>(ga);
    ga = {XN, Wkv1, nullptr, nullptr, K, 1.f, NTX, C_, C_, C_, 2*C_, C_, 0,0,0,0,0,0, 1};
    launch_mma<0,0>(ga);
    ga = {XN, Wkv1 + C_, nullptr, nullptr, V, 1.f, NTX, C_, C_, C_, 2*C_, C_, 0,0,0,0,0,0, 1};
    launch_mma<0,0>(ga);

    // scores: per (b,h)  P = Q @ K^T * scale   [L x L]
    ga = {Q, K, nullptr, nullptr, P, scale, L_, L_, D_, C_, C_, L_,
          (long long)L_*C_, D_, (long long)L_*C_, D_,
          (long long)H_*L_*L_, (long long)L_*L_, B_*H_};
    launch_mma<1,1>(ga);
    softmax_kernel<<<dim3(L_, B_*H_), 256>>>(P, eff, usr, L_, L_, 1);
    // attn out: AO = P @ V   [L x 96] per (b,h)
    ga = {P, V, nullptr, nullptr, AO, 1.f, L_, D_, L_, L_, C_, C_,
          (long long)H_*L_*L_, (long long)L_*L_,
          (long long)L_*C_, D_, (long long)L_*C_, D_, B_*H_};
    launch_mma<0,0>(ga);

    ga = {AO, Wo1, bo1, x, X2, 1.f, NTX, C_, C_, C_, C_, C_, 0,0,0,0,0,0, 1};
    launch_mma<3,0>(ga);

    // ---------- cross-attention ----------
    ln_kernel<<<NTX, 256>>>(X2, g2, b2, XN);
    ln_kernel<<<NTC, 256>>>(c,  gc, bc, CN);

    ga = {XN, Wq2, nullptr, nullptr, Q, 1.f, NTX, C_, C_, C_, C_, C_, 0,0,0,0,0,0, 1};
    launch_mma<0,0>(ga);
    ga = {CN, Wkv2, nullptr, nullptr, K, 1.f, NTC, C_, C_, C_, 2*C_, C_, 0,0,0,0,0,0, 1};
    launch_mma<0,0>(ga);
    ga = {CN, Wkv2 + C_, nullptr, nullptr, V, 1.f, NTC, C_, C_, C_, 2*C_, C_, 0,0,0,0,0,0, 1};
    launch_mma<0,0>(ga);

    ga = {Q, K, nullptr, nullptr, P, scale, L_, S_, D_, C_, C_, S_,
          (long long)L_*C_, D_, (long long)S_*C_, D_,
          (long long)H_*L_*S_, (long long)L_*S_, B_*H_};
    launch_mma<1,1>(ga);
    softmax_kernel<<<dim3(L_, B_*H_), 256>>>(P, eff, usr, L_, S_, 0);
    ga = {P, V, nullptr, nullptr, AO, 1.f, L_, D_, S_, S_, C_, C_,
          (long long)H_*L_*S_, (long long)L_*S_,
          (long long)S_*C_, D_, (long long)L_*C_, D_, B_*H_};
    launch_mma<0,0>(ga);

    ga = {AO, Wo2, bo2, X2, X2, 1.f, NTX, C_, C_, C_, C_, C_, 0,0,0,0,0,0, 1};
    launch_mma<3,0>(ga);

    // ---------- FFN ----------
    ln_kernel<<<NTX, 256>>>(X2, g4, b4, XN);
    ga = {XN, Wf1, bf1, nullptr, Hf, 1.f, NTX, F_, C_, C_, F_, F_, 0,0,0,0,0,0, 1};
    launch_mma<2,0>(ga);
    ga = {Hf, Wf2, bf2, X2, out, 1.f, NTX, C_, F_, F_, C_, C_, 0,0,0,0,0,0, 1};
    launch_mma<3,0>(ga);
}

// round 4
// speedup vs baseline: 2.4471x; 1.6468x over previous
#include <cuda_runtime.h>
#include <cuda_bf16.h>
#include <math.h>
#include <stdint.h>

#define B_  8
#define L_  1024
#define S_  512
#define C_  768
#define H_  8
#define D_  96
#define F_  3072
#define NTX (B_*L_)
#define NTC (B_*S_)

// ---------------- scratch (+pad for benign OOB B-tile reads at N=96 tiles) ----------------
__device__ float g_XN[(size_t)NTX*C_ + 64];
__device__ float g_CN[(size_t)NTC*C_ + 64];
__device__ float g_Q [(size_t)NTX*C_ + 64];
__device__ float g_KV[(size_t)NTX*2*C_ + 64];
__device__ float g_AO[(size_t)NTX*C_ + 64];
__device__ float g_X2[(size_t)NTX*C_ + 64];
__device__ float g_P [(size_t)B_*H_*L_*L_ + 64];
__device__ float g_H [(size_t)NTX*F_ + 64];

// ---------------- reductions ----------------
__device__ __forceinline__ float blockReduceSum(float v) {
    __shared__ float sh[32];
    __syncthreads();
    int lane = threadIdx.x & 31, wid = threadIdx.x >> 5;
    #pragma unroll
    for (int o = 16; o; o >>= 1) v += __shfl_down_sync(0xffffffffu, v, o);
    if (lane == 0) sh[wid] = v;
    __syncthreads();
    int nw = blockDim.x >> 5;
    v = (threadIdx.x < nw) ? sh[threadIdx.x] : 0.0f;
    if (wid == 0) {
        #pragma unroll
        for (int o = 16; o; o >>= 1) v += __shfl_down_sync(0xffffffffu, v, o);
        if (lane == 0) sh[0] = v;
    }
    __syncthreads();
    return sh[0];
}

__device__ __forceinline__ float blockReduceMax(float v) {
    __shared__ float sh[32];
    __syncthreads();
    int lane = threadIdx.x & 31, wid = threadIdx.x >> 5;
    #pragma unroll
    for (int o = 16; o; o >>= 1) v = fmaxf(v, __shfl_down_sync(0xffffffffu, v, o));
    if (lane == 0) sh[wid] = v;
    __syncthreads();
    int nw = blockDim.x >> 5;
    v = (threadIdx.x < nw) ? sh[threadIdx.x] : -3.4e38f;
    if (wid == 0) {
        #pragma unroll
        for (int o = 16; o; o >>= 1) v = fmaxf(v, __shfl_down_sync(0xffffffffu, v, o));
        if (lane == 0) sh[0] = v;
    }
    __syncthreads();
    return sh[0];
}

// ---------------- layernorm ----------------
__global__ void ln_kernel(const float* __restrict__ X,
                          const float* __restrict__ g, const float* __restrict__ b,
                          float* __restrict__ Y) {
    const int row = blockIdx.x;
    const float* x = X + (size_t)row * C_;
    float s = 0.f, s2 = 0.f;
    for (int j = threadIdx.x; j < C_; j += blockDim.x) {
        float v = x[j];
        s += v; s2 += v * v;
    }
    s  = blockReduceSum(s);
    s2 = blockReduceSum(s2);
    const float mean = s * (1.0f / C_);
    const float var  = s2 * (1.0f / C_) - mean * mean;
    const float inv  = rsqrtf(var + 1e-5f);
    float* y = Y + (size_t)row * C_;
    for (int j = threadIdx.x; j < C_; j += blockDim.x)
        y[j] = (x[j] - mean) * inv * g[j] + b[j];
}

// ---------------- masked softmax (2-pass exp) ----------------
__global__ void softmax_kernel(float* __restrict__ P, const int* __restrict__ eff,
                               const int* __restrict__ usp, int Lq, int Lk, int self_mode) {
    const int bh = blockIdx.y, b = bh / H_, i = blockIdx.x;
    float* row = P + ((size_t)bh * Lq + i) * Lk;
    const int us = usp[0];
    const int el = eff[b] * us;
    const int jl = self_mode ? el : eff[b];

    if (i >= el) {
        const float u = 1.0f / (float)Lk;
        for (int j = threadIdx.x; j < Lk; j += blockDim.x) row[j] = u;
        return;
    }
    float m = -3.4e38f;
    for (int j = threadIdx.x; j < jl; j += blockDim.x) m = fmaxf(m, row[j]);
    m = blockReduceMax(m);
    float s = 0.f;
    for (int j = threadIdx.x; j < jl; j += blockDim.x) {
        float e = expf(row[j] - m);
        row[j] = e;
        s += e;
    }
    s = blockReduceSum(s);
    const float inv = 1.0f / s;
    for (int j = threadIdx.x; j < Lk; j += blockDim.x)
        row[j] = (j < jl) ? row[j] * inv : 0.0f;
}

// ---------------- tf32 tensor-core GEMM, cp.async double-buffered ----------------
// C[M,N] = A[M,K] @ B ; TRANSB: B given as [N,K] row-major (use B^T)
// Tiles 128x128x32, 8 warps (64m x 32n per warp), m16n8k8 tf32 mma.
// fp32 bits fed directly as tf32 (HW truncation).
// EPI: 0 store, 1 scale*acc, 2 bias+gelu, 3 bias+residual
#define AS_LD 36     // [m][k] stride (conflict-free: (4m+k)%32 distinct)
#define BSN_LD 136   // [k][n] stride (conflict-free: (8k+n)%32 distinct)

__device__ __forceinline__ void cpa16(uint32_t dst, const float* src) {
    asm volatile("cp.async.cg.shared.global [%0], [%1], 16;\n" :: "r"(dst), "l"(src));
}

template <int EPI, int TRANSB>
__global__ __launch_bounds__(256, 2)
void mma_gemm(const float* __restrict__ A, const float* __restrict__ Bm,
              const float* __restrict__ bias, const float* __restrict__ R,
              float* __restrict__ Cc, float scale,
              int M, int N, int K, int lda, int ldb, int ldc,
              long long aBS, long long aHS,
              long long bBS, long long bHS,
              long long cBS, long long cHS) {
    extern __shared__ float smem[];
    constexpr int ASZ = 128 * AS_LD;                    // floats per A buffer
    constexpr int BSZ = TRANSB ? 128 * AS_LD : 32 * BSN_LD;
    float* As = smem;
    float* Bs = smem + 2 * ASZ;
    const uint32_t sa = (uint32_t)__cvta_generic_to_shared(As);
    const uint32_t sb = (uint32_t)__cvta_generic_to_shared(Bs);

    const int z = blockIdx.z, zb = z / H_, zh = z % H_;
    const float* Ab = A  + (size_t)zb * aBS + (size_t)zh * aHS;
    const float* Bb = Bm + (size_t)zb * bBS + (size_t)zh * bHS;
    float*       Cb = Cc + (size_t)zb * cBS + (size_t)zh * cHS;

    const int m0 = blockIdx.y * 128, n0 = blockIdx.x * 128;
    const int tid = threadIdx.x, lane = tid & 31, warp = tid >> 5;
    const int wm = (warp & 1) * 64;
    const int wn = (warp >> 1) * 32;
    const int g = lane >> 2, tg = lane & 3;

    float acc[4][4][4] = {};

    const int nIter = K >> 5;

    auto load_tile = [&](int it, int buf) {
        const int kbase = it * 32;
        #pragma unroll
        for (int i = 0; i < 4; i++) {
            int fid = tid + i * 256;
            int m = fid >> 3, kc = (fid & 7) * 4;
            cpa16(sa + (uint32_t)((buf * ASZ + m * AS_LD + kc) << 2),
                  Ab + (size_t)(m0 + m) * lda + kbase + kc);
        }
        if (TRANSB) {
            #pragma unroll
            for (int i = 0; i < 4; i++) {
                int fid = tid + i * 256;
                int n = fid >> 3, kc = (fid & 7) * 4;
                cpa16(sb + (uint32_t)((buf * BSZ + n * AS_LD + kc) << 2),
                      Bb + (size_t)(n0 + n) * ldb + kbase + kc);
            }
        } else {
            #pragma unroll
            for (int i = 0; i < 4; i++) {
                int fid = tid + i * 256;
                int k = fid >> 5, nc = (fid & 31) * 4;
                cpa16(sb + (uint32_t)((buf * BSZ + k * BSN_LD + nc) << 2),
                      Bb + (size_t)(kbase + k) * ldb + n0 + nc);
            }
        }
        asm volatile("cp.async.commit_group;\n");
    };

    load_tile(0, 0);

    for (int it = 0; it < nIter; it++) {
        const int buf = it & 1;
        if (it + 1 < nIter) {
            load_tile(it + 1, buf ^ 1);
            asm volatile("cp.async.wait_group 1;\n");
        } else {
            asm volatile("cp.async.wait_group 0;\n");
        }
        __syncthreads();

        const float* Asb = As + buf * ASZ;
        const float* Bsb = Bs + buf * BSZ;
        #pragma unroll
        for (int kk = 0; kk < 32; kk += 8) {
            unsigned a[4][4], bfr[4][2];
            #pragma unroll
            for (int mi = 0; mi < 4; mi++) {
                const float* ap = Asb + (wm + mi * 16 + g) * AS_LD + kk + tg;
                a[mi][0] = __float_as_uint(ap[0]);
                a[mi][2] = __float_as_uint(ap[4]);
                a[mi][1] = __float_as_uint(ap[8 * AS_LD]);
                a[mi][3] = __float_as_uint(ap[8 * AS_LD + 4]);
            }
            #pragma unroll
            for (int ni = 0; ni < 4; ni++) {
                if (TRANSB) {
                    const float* bp = Bsb + (wn + ni * 8 + g) * AS_LD + kk + tg;
                    bfr[ni][0] = __float_as_uint(bp[0]);
                    bfr[ni][1] = __float_as_uint(bp[4]);
                } else {
                    bfr[ni][0] = __float_as_uint(Bsb[(kk + tg) * BSN_LD + wn + ni * 8 + g]);
                    bfr[ni][1] = __float_as_uint(Bsb[(kk + 4 + tg) * BSN_LD + wn + ni * 8 + g]);
                }
            }
            #pragma unroll
            for (int mi = 0; mi < 4; mi++)
                #pragma unroll
                for (int ni = 0; ni < 4; ni++) {
                    asm volatile(
                        "mma.sync.aligned.m16n8k8.row.col.f32.tf32.tf32.f32 "
                        "{%0,%1,%2,%3}, {%4,%5,%6,%7}, {%8,%9}, {%0,%1,%2,%3};"
                        : "+f"(acc[mi][ni][0]), "+f"(acc[mi][ni][1]),
                          "+f"(acc[mi][ni][2]), "+f"(acc[mi][ni][3])
                        : "r"(a[mi][0]), "r"(a[mi][1]), "r"(a[mi][2]), "r"(a[mi][3]),
                          "r"(bfr[ni][0]), "r"(bfr[ni][1]));
                }
        }
        __syncthreads();
    }

    // ---- epilogue ----
    #pragma unroll
    for (int mi = 0; mi < 4; mi++) {
        const int r0 = m0 + wm + mi * 16 + g;
        const int r1 = r0 + 8;
        #pragma unroll
        for (int ni = 0; ni < 4; ni++) {
            const int cc = n0 + wn + ni * 8 + 2 * tg;
            float v00 = acc[mi][ni][0], v01 = acc[mi][ni][1];
            float v10 = acc[mi][ni][2], v11 = acc[mi][ni][3];
            if (EPI == 1) { v00 *= scale; v01 *= scale; v10 *= scale; v11 *= scale; }
            if (EPI >= 2) {
                float bz0 = (cc < N) ? bias[cc] : 0.f;
                float bz1 = (cc + 1 < N) ? bias[cc + 1] : 0.f;
                v00 += bz0; v01 += bz1; v10 += bz0; v11 += bz1;
            }
            if (EPI == 2) {
                v00 = 0.5f * v00 * (1.0f + erff(v00 * 0.70710678118654752f));
                v01 = 0.5f * v01 * (1.0f + erff(v01 * 0.70710678118654752f));
                v10 = 0.5f * v10 * (1.0f + erff(v10 * 0.70710678118654752f));
                v11 = 0.5f * v11 * (1.0f + erff(v11 * 0.70710678118654752f));
            }
            if (EPI == 3) {
                if (cc < N) {
                    v00 += R[(size_t)r0 * ldc + cc];
                    v10 += R[(size_t)r1 * ldc + cc];
                }
                if (cc + 1 < N) {
                    v01 += R[(size_t)r0 * ldc + cc + 1];
                    v11 += R[(size_t)r1 * ldc + cc + 1];
                }
            }
            if (cc < N) {
                Cb[(size_t)r0 * ldc + cc] = v00;
                Cb[(size_t)r1 * ldc + cc] = v10;
            }
            if (cc + 1 < N) {
                Cb[(size_t)r0 * ldc + cc + 1] = v01;
                Cb[(size_t)r1 * ldc + cc + 1] = v11;
            }
        }
    }
}

// ---------------- host-side launch helpers ----------------
struct GemmArgs {
    const float *A, *B, *bias, *R;
    float *C;
    float scale;
    int M, N, K, lda, ldb, ldc;
    long long aBS, aHS, bBS, bHS, cBS, cHS;
    int batches;
};

template <int EPI, int TRANSB>
static void launch_mma(const GemmArgs& a) {
    constexpr int ASZ = 128 * AS_LD;
    constexpr int BSZ = TRANSB ? 128 * AS_LD : 32 * BSN_LD;
    const int smemBytes = (2 * ASZ + 2 * BSZ) * 4;
    cudaFuncSetAttribute(mma_gemm<EPI, TRANSB>,
                         cudaFuncAttributeMaxDynamicSharedMemorySize, smemBytes);
    dim3 grid((a.N + 127) / 128, a.M / 128, a.batches), blk(256);
    mma_gemm<EPI, TRANSB><<<grid, blk, smemBytes>>>(
        a.A, a.B, a.bias, a.R, a.C, a.scale,
        a.M, a.N, a.K, a.lda, a.ldb, a.ldc,
        a.aBS, a.aHS, a.bBS, a.bHS, a.cBS, a.cHS);
}

extern "C" void kernel_launch(void* const* d_in, const int* in_sizes, int n_in,
                              void* d_out, int out_size) {
    const float* x    = (const float*)d_in[0];
    const float* c    = (const float*)d_in[1];
    const int*   eff  = (const int*)  d_in[2];
    const int*   usr  = (const int*)  d_in[3];
    const float* Wq1  = (const float*)d_in[4];
    const float* Wkv1 = (const float*)d_in[5];
    const float* Wo1  = (const float*)d_in[6];
    const float* bo1  = (const float*)d_in[7];
    const float* Wq2  = (const float*)d_in[8];
    const float* Wkv2 = (const float*)d_in[9];
    const float* Wo2  = (const float*)d_in[10];
    const float* bo2  = (const float*)d_in[11];
    const float* g1   = (const float*)d_in[12];
    const float* b1   = (const float*)d_in[13];
    const float* g2   = (const float*)d_in[14];
    const float* b2   = (const float*)d_in[15];
    const float* g4   = (const float*)d_in[16];
    const float* b4   = (const float*)d_in[17];
    const float* gc   = (const float*)d_in[18];
    const float* bc   = (const float*)d_in[19];
    const float* Wf1  = (const float*)d_in[20];
    const float* bf1  = (const float*)d_in[21];
    const float* Wf2  = (const float*)d_in[22];
    const float* bf2  = (const float*)d_in[23];
    float* out = (float*)d_out;

    float *XN, *CN, *Q, *KV, *AO, *X2, *P, *Hf;
    cudaGetSymbolAddress((void**)&XN, g_XN);
    cudaGetSymbolAddress((void**)&CN, g_CN);
    cudaGetSymbolAddress((void**)&Q,  g_Q);
    cudaGetSymbolAddress((void**)&KV, g_KV);
    cudaGetSymbolAddress((void**)&AO, g_AO);
    cudaGetSymbolAddress((void**)&X2, g_X2);
    cudaGetSymbolAddress((void**)&P,  g_P);
    cudaGetSymbolAddress((void**)&Hf, g_H);

    const float scale = rsqrtf((float)D_);
    GemmArgs ga;

    // ---------- self-attention ----------
    ln_kernel<<<NTX, 256>>>(x, g1, b1, XN);

    ga = {XN, Wq1, nullptr, nullptr, Q, 1.f, NTX, C_, C_, C_, C_, C_, 0,0,0,0,0,0, 1};
    launch_mma<0,0>(ga);
    ga = {XN, Wkv1, nullptr, nullptr, KV, 1.f, NTX, 2*C_, C_, C_, 2*C_, 2*C_, 0,0,0,0,0,0, 1};
    launch_mma<0,0>(ga);

    // scores: P = Q @ K^T * scale  per (b,h)
    ga = {Q, KV, nullptr, nullptr, P, scale, L_, L_, D_, C_, 2*C_, L_,
          (long long)L_*C_, D_, (long long)L_*2*C_, D_,
          (long long)H_*L_*L_, (long long)L_*L_, B_*H_};
    launch_mma<1,1>(ga);
    softmax_kernel<<<dim3(L_, B_*H_), 256>>>(P, eff, usr, L_, L_, 1);
    // attn out: AO = P @ V
    ga = {P, KV + C_, nullptr, nullptr, AO, 1.f, L_, D_, L_, L_, 2*C_, C_,
          (long long)H_*L_*L_, (long long)L_*L_,
          (long long)L_*2*C_, D_, (long long)L_*C_, D_, B_*H_};
    launch_mma<0,0>(ga);

    ga = {AO, Wo1, bo1, x, X2, 1.f, NTX, C_, C_, C_, C_, C_, 0,0,0,0,0,0, 1};
    launch_mma<3,0>(ga);

    // ---------- cross-attention ----------
    ln_kernel<<<NTX, 256>>>(X2, g2, b2, XN);
    ln_kernel<<<NTC, 256>>>(c,  gc, bc, CN);

    ga = {XN, Wq2, nullptr, nullptr, Q, 1.f, NTX, C_, C_, C_, C_, C_, 0,0,0,0,0,0, 1};
    launch_mma<0,0>(ga);
    ga = {CN, Wkv2, nullptr, nullptr, KV, 1.f, NTC, 2*C_, C_, C_, 2*C_, 2*C_, 0,0,0,0,0,0, 1};
    launch_mma<0,0>(ga);

    ga = {Q, KV, nullptr, nullptr, P, scale, L_, S_, D_, C_, 2*C_, S_,
          (long long)L_*C_, D_, (long long)S_*2*C_, D_,
          (long long)H_*L_*S_, (long long)L_*S_, B_*H_};
    launch_mma<1,1>(ga);
    softmax_kernel<<<dim3(L_, B_*H_), 256>>>(P, eff, usr, L_, S_, 0);
    ga = {P, KV + C_, nullptr, nullptr, AO, 1.f, L_, D_, S_, S_, 2*C_, C_,
          (long long)H_*L_*S_, (long long)L_*S_,
          (long long)S_*2*C_, D_, (long long)L_*C_, D_, B_*H_};
    launch_mma<0,0>(ga);

    ga = {AO, Wo2, bo2, X2, X2, 1.f, NTX, C_, C_, C_, C_, C_, 0,0,0,0,0,0, 1};
    launch_mma<3,0>(ga);

    // ---------- FFN ----------
    ln_kernel<<<NTX, 256>>>(X2, g4, b4, XN);
    ga = {XN, Wf1, bf1, nullptr, Hf, 1.f, NTX, F_, C_, C_, F_, F_, 0,0,0,0,0,0, 1};
    launch_mma<2,0>(ga);
    ga = {Hf, Wf2, bf2, X2, out, 1.f, NTX, C_, F_, F_, C_, C_, 0,0,0,0,0,0, 1};
    launch_mma<3,0>(ga);
}

// round 5
// speedup vs baseline: 4.5136x; 1.8445x over previous
#include <cuda_runtime.h>
#include <cuda_bf16.h>
#include <math.h>
#include <stdint.h>

#define B_  8
#define L_  1024
#define S_  512
#define C_  768
#define H_  8
#define D_  96
#define F_  3072
#define NTX (B_*L_)
#define NTC (B_*S_)

// ---------------- scratch ----------------
__device__ float g_XN[(size_t)NTX*C_ + 64];
__device__ float g_CN[(size_t)NTC*C_ + 64];
__device__ float g_Q [(size_t)NTX*C_ + 64];
__device__ float g_KV[(size_t)NTX*2*C_ + 64];
__device__ float g_AO[(size_t)NTX*C_ + 64];
__device__ float g_X2[(size_t)NTX*C_ + 64];
__device__ float g_H [(size_t)NTX*F_ + 64];
__device__ float g_VM[(size_t)B_*H_*D_ + 64];

// ---------------- reductions ----------------
__device__ __forceinline__ float blockReduceSum(float v) {
    __shared__ float sh[32];
    __syncthreads();
    int lane = threadIdx.x & 31, wid = threadIdx.x >> 5;
    #pragma unroll
    for (int o = 16; o; o >>= 1) v += __shfl_down_sync(0xffffffffu, v, o);
    if (lane == 0) sh[wid] = v;
    __syncthreads();
    int nw = blockDim.x >> 5;
    v = (threadIdx.x < nw) ? sh[threadIdx.x] : 0.0f;
    if (wid == 0) {
        #pragma unroll
        for (int o = 16; o; o >>= 1) v += __shfl_down_sync(0xffffffffu, v, o);
        if (lane == 0) sh[0] = v;
    }
    __syncthreads();
    return sh[0];
}

// ---------------- layernorm ----------------
__global__ void ln_kernel(const float* __restrict__ X,
                          const float* __restrict__ g, const float* __restrict__ b,
                          float* __restrict__ Y) {
    const int row = blockIdx.x;
    const float* x = X + (size_t)row * C_;
    float s = 0.f, s2 = 0.f;
    for (int j = threadIdx.x; j < C_; j += blockDim.x) {
        float v = x[j];
        s += v; s2 += v * v;
    }
    s  = blockReduceSum(s);
    s2 = blockReduceSum(s2);
    const float mean = s * (1.0f / C_);
    const float var  = s2 * (1.0f / C_) - mean * mean;
    const float inv  = rsqrtf(var + 1e-5f);
    float* y = Y + (size_t)row * C_;
    for (int j = threadIdx.x; j < C_; j += blockDim.x)
        y[j] = (x[j] - mean) * inv * g[j] + b[j];
}

// ---------------- cp.async helper ----------------
__device__ __forceinline__ void cpa16(uint32_t dst, const float* src) {
    asm volatile("cp.async.cg.shared.global [%0], [%1], 16;\n" :: "r"(dst), "l"(src));
}

__device__ __forceinline__ void mma_tf32(float* d, const unsigned* a, const unsigned* b) {
    asm volatile(
        "mma.sync.aligned.m16n8k8.row.col.f32.tf32.tf32.f32 "
        "{%0,%1,%2,%3}, {%4,%5,%6,%7}, {%8,%9}, {%0,%1,%2,%3};"
        : "+f"(d[0]), "+f"(d[1]), "+f"(d[2]), "+f"(d[3])
        : "r"(a[0]), "r"(a[1]), "r"(a[2]), "r"(a[3]), "r"(b[0]), "r"(b[1]));
}

// ---------------- V column mean per (b,h): for fully-masked query rows ----------------
__global__ void vmean_kernel(const float* __restrict__ KVg, float* __restrict__ VM, int Lk) {
    const int bh = blockIdx.x, b = bh >> 3, h = bh & 7;
    const float* Vb = KVg + (size_t)b * Lk * (2*C_) + C_ + h * D_;
    const int cc = threadIdx.x;    // blockDim = 96
    float s = 0.f;
    #pragma unroll 4
    for (int j = 0; j < Lk; j++) s += Vb[(size_t)j * (2*C_) + cc];
    VM[bh * D_ + cc] = s / (float)Lk;
}

// ---------------- flash attention (tf32 mma, online softmax) ----------------
// Q block 128 rows, key tiles of 64, 8 warps x 16 rows, d=96.
// Valid rows (i<el): softmax over keys j<jl. Masked rows (i>=el): output = mean(V).
#define FQ 128
#define FK 64
#define QLD 100
#define KLD 100
#define VLD 104
#define PLD 68

__global__ __launch_bounds__(256)
void flash_kernel(const float* __restrict__ Qg, const float* __restrict__ KVg,
                  const float* __restrict__ VM, float* __restrict__ AO,
                  const int* __restrict__ eff, const int* __restrict__ usp,
                  int Lk, int self_mode) {
    extern __shared__ float sm[];
    float* Qs = sm;                       // FQ x QLD
    float* Ks = Qs + FQ*QLD;              // 2 x FK x KLD
    float* Vs = Ks + 2*FK*KLD;            // 2 x FK x VLD
    float* Ps = Vs + 2*FK*VLD;            // FQ x PLD

    const int bh = blockIdx.y, b = bh >> 3, h = bh & 7;
    const int i0 = blockIdx.x * FQ;
    const int e  = eff[b];
    const int el = e * usp[0];
    const int jl = self_mode ? el : e;

    const int tid = threadIdx.x, lane = tid & 31, warp = tid >> 5;
    const int g = lane >> 2, tg = lane & 3;
    const int wm = warp * 16;

    const float* Qrow = Qg + ((size_t)b * L_ + i0) * C_ + h * D_;
    const float* Kb   = KVg + (size_t)b * Lk * (2*C_) + h * D_;
    const float* Vb   = Kb + C_;
    float*       AOb  = AO + ((size_t)b * L_ + i0) * C_ + h * D_;

    // fill masked rows (i >= el) with V-mean
    const int rm0 = (el > i0) ? ((el - i0 < FQ) ? (el - i0) : FQ) : 0;
    if (rm0 < FQ) {
        const float* vm = VM + bh * D_;
        for (int idx = tid; idx < (FQ - rm0) * D_; idx += 256) {
            int r = rm0 + idx / D_, cc = idx % D_;
            AOb[(size_t)r * C_ + cc] = vm[cc];
        }
    }
    if (rm0 == 0) return;   // whole block masked

    // async-load Q tile
    {
        const uint32_t sq = (uint32_t)__cvta_generic_to_shared(Qs);
        for (int t = tid; t < FQ * 24; t += 256) {
            int r = t / 24, cq = (t % 24) * 4;
            cpa16(sq + (uint32_t)((r * QLD + cq) << 2), Qrow + (size_t)r * C_ + cq);
        }
        asm volatile("cp.async.commit_group;\n");
    }

    const uint32_t sk = (uint32_t)__cvta_generic_to_shared(Ks);
    const uint32_t sv = (uint32_t)__cvta_generic_to_shared(Vs);
    const int nkt = (jl + FK - 1) / FK;

    auto load_kv = [&](int t, int buf) {
        const int j0 = t * FK;
        for (int i = tid; i < FK * 24; i += 256) {
            int r = i / 24, cq = (i % 24) * 4;
            const size_t off = (size_t)(j0 + r) * (2*C_) + cq;
            cpa16(sk + (uint32_t)((buf * FK * KLD + r * KLD + cq) << 2), Kb + off);
            cpa16(sv + (uint32_t)((buf * FK * VLD + r * VLD + cq) << 2), Vb + off);
        }
        asm volatile("cp.async.commit_group;\n");
    };

    load_kv(0, 0);
    asm volatile("cp.async.wait_group 0;\n");
    __syncthreads();

    // Q fragments (pre-scaled by 1/sqrt(d))
    const float scale = rsqrtf((float)D_);
    unsigned qf[12][4];
    #pragma unroll
    for (int kk = 0; kk < 12; kk++) {
        qf[kk][0] = __float_as_uint(Qs[(wm+g  )*QLD + kk*8 + tg    ] * scale);
        qf[kk][1] = __float_as_uint(Qs[(wm+g+8)*QLD + kk*8 + tg    ] * scale);
        qf[kk][2] = __float_as_uint(Qs[(wm+g  )*QLD + kk*8 + tg + 4] * scale);
        qf[kk][3] = __float_as_uint(Qs[(wm+g+8)*QLD + kk*8 + tg + 4] * scale);
    }

    float Oacc[12][4] = {};
    float m0 = -1e30f, m1 = -1e30f, l0 = 0.f, l1 = 0.f;

    for (int t = 0; t < nkt; t++) {
        const int buf = t & 1;
        if (t + 1 < nkt) {
            load_kv(t + 1, buf ^ 1);
            asm volatile("cp.async.wait_group 1;\n");
        } else {
            asm volatile("cp.async.wait_group 0;\n");
        }
        __syncthreads();

        const float* Kst = Ks + buf * FK * KLD;
        const float* Vst = Vs + buf * FK * VLD;

        // ---- S = Q @ K^T (scaled) ----
        float sacc[8][4] = {};
        #pragma unroll
        for (int kk = 0; kk < 12; kk++) {
            unsigned bf[8][2];
            #pragma unroll
            for (int ni = 0; ni < 8; ni++) {
                bf[ni][0] = __float_as_uint(Kst[(ni*8+g)*KLD + kk*8 + tg    ]);
                bf[ni][1] = __float_as_uint(Kst[(ni*8+g)*KLD + kk*8 + tg + 4]);
            }
            #pragma unroll
            for (int ni = 0; ni < 8; ni++)
                mma_tf32(sacc[ni], qf[kk], bf[ni]);
        }

        // ---- mask ----
        const int jb = t * FK + 2*tg;
        #pragma unroll
        for (int ni = 0; ni < 8; ni++) {
            const int j = jb + ni*8;
            if (j     >= jl) { sacc[ni][0] = -1e30f; sacc[ni][2] = -1e30f; }
            if (j + 1 >= jl) { sacc[ni][1] = -1e30f; sacc[ni][3] = -1e30f; }
        }

        // ---- online softmax (rows g, g+8) ----
        float mx0 = -1e30f, mx1 = -1e30f;
        #pragma unroll
        for (int ni = 0; ni < 8; ni++) {
            mx0 = fmaxf(mx0, fmaxf(sacc[ni][0], sacc[ni][1]));
            mx1 = fmaxf(mx1, fmaxf(sacc[ni][2], sacc[ni][3]));
        }
        mx0 = fmaxf(mx0, __shfl_xor_sync(0xffffffffu, mx0, 1));
        mx0 = fmaxf(mx0, __shfl_xor_sync(0xffffffffu, mx0, 2));
        mx1 = fmaxf(mx1, __shfl_xor_sync(0xffffffffu, mx1, 1));
        mx1 = fmaxf(mx1, __shfl_xor_sync(0xffffffffu, mx1, 2));
        const float nm0 = fmaxf(m0, mx0), nm1 = fmaxf(m1, mx1);
        const float a0 = __expf(m0 - nm0), a1 = __expf(m1 - nm1);
        float rs0 = 0.f, rs1 = 0.f;
        #pragma unroll
        for (int ni = 0; ni < 8; ni++) {
            sacc[ni][0] = __expf(sacc[ni][0] - nm0);
            sacc[ni][1] = __expf(sacc[ni][1] - nm0);
            sacc[ni][2] = __expf(sacc[ni][2] - nm1);
            sacc[ni][3] = __expf(sacc[ni][3] - nm1);
            rs0 += sacc[ni][0] + sacc[ni][1];
            rs1 += sacc[ni][2] + sacc[ni][3];
        }
        rs0 += __shfl_xor_sync(0xffffffffu, rs0, 1);
        rs0 += __shfl_xor_sync(0xffffffffu, rs0, 2);
        rs1 += __shfl_xor_sync(0xffffffffu, rs1, 1);
        rs1 += __shfl_xor_sync(0xffffffffu, rs1, 2);
        l0 = l0 * a0 + rs0;
        l1 = l1 * a1 + rs1;
        m0 = nm0; m1 = nm1;
        #pragma unroll
        for (int nj = 0; nj < 12; nj++) {
            Oacc[nj][0] *= a0; Oacc[nj][1] *= a0;
            Oacc[nj][2] *= a1; Oacc[nj][3] *= a1;
        }

        // ---- stage P (per-warp-private rows) ----
        #pragma unroll
        for (int ni = 0; ni < 8; ni++) {
            *(float2*)&Ps[(wm+g  )*PLD + ni*8 + 2*tg] = make_float2(sacc[ni][0], sacc[ni][1]);
            *(float2*)&Ps[(wm+g+8)*PLD + ni*8 + 2*tg] = make_float2(sacc[ni][2], sacc[ni][3]);
        }
        __syncwarp();

        // ---- O += P @ V ----
        #pragma unroll
        for (int kk = 0; kk < 8; kk++) {
            unsigned af[4];
            af[0] = __float_as_uint(Ps[(wm+g  )*PLD + kk*8 + tg    ]);
            af[1] = __float_as_uint(Ps[(wm+g+8)*PLD + kk*8 + tg    ]);
            af[2] = __float_as_uint(Ps[(wm+g  )*PLD + kk*8 + tg + 4]);
            af[3] = __float_as_uint(Ps[(wm+g+8)*PLD + kk*8 + tg + 4]);
            #pragma unroll
            for (int nj = 0; nj < 12; nj++) {
                unsigned bv[2];
                bv[0] = __float_as_uint(Vst[(kk*8+tg  )*VLD + nj*8 + g]);
                bv[1] = __float_as_uint(Vst[(kk*8+tg+4)*VLD + nj*8 + g]);
                mma_tf32(Oacc[nj], af, bv);
            }
        }
        __syncthreads();   // protect K/V buffers before next prefetch
    }

    // ---- epilogue: normalize and write valid rows ----
    const float inv0 = 1.f / l0, inv1 = 1.f / l1;
    const int i_r0 = i0 + wm + g, i_r1 = i_r0 + 8;
    #pragma unroll
    for (int nj = 0; nj < 12; nj++) {
        const int ccol = nj*8 + 2*tg;
        if (i_r0 < el)
            *(float2*)&AOb[(size_t)(wm+g  )*C_ + ccol] =
                make_float2(Oacc[nj][0]*inv0, Oacc[nj][1]*inv0);
        if (i_r1 < el)
            *(float2*)&AOb[(size_t)(wm+g+8)*C_ + ccol] =
                make_float2(Oacc[nj][2]*inv1, Oacc[nj][3]*inv1);
    }
}

// ---------------- tf32 tensor-core GEMM, cp.async double-buffered ----------------
#define AS_LD 36
#define BSN_LD 136

template <int EPI, int TRANSB>
__global__ __launch_bounds__(256, 2)
void mma_gemm(const float* __restrict__ A, const float* __restrict__ Bm,
              const float* __restrict__ bias, const float* __restrict__ R,
              float* __restrict__ Cc, float scale,
              int M, int N, int K, int lda, int ldb, int ldc) {
    extern __shared__ float smem[];
    constexpr int ASZ = 128 * AS_LD;
    constexpr int BSZ = TRANSB ? 128 * AS_LD : 32 * BSN_LD;
    float* As = smem;
    float* Bs = smem + 2 * ASZ;
    const uint32_t sa = (uint32_t)__cvta_generic_to_shared(As);
    const uint32_t sb = (uint32_t)__cvta_generic_to_shared(Bs);

    const float* Ab = A;
    const float* Bb = Bm;
    float*       Cb = Cc;

    const int m0 = blockIdx.y * 128, n0 = blockIdx.x * 128;
    const int tid = threadIdx.x, lane = tid & 31, warp = tid >> 5;
    const int wm = (warp & 1) * 64;
    const int wn = (warp >> 1) * 32;
    const int g = lane >> 2, tg = lane & 3;

    float acc[4][4][4] = {};
    const int nIter = K >> 5;

    auto load_tile = [&](int it, int buf) {
        const int kbase = it * 32;
        #pragma unroll
        for (int i = 0; i < 4; i++) {
            int fid = tid + i * 256;
            int m = fid >> 3, kc = (fid & 7) * 4;
            cpa16(sa + (uint32_t)((buf * ASZ + m * AS_LD + kc) << 2),
                  Ab + (size_t)(m0 + m) * lda + kbase + kc);
        }
        if (TRANSB) {
            #pragma unroll
            for (int i = 0; i < 4; i++) {
                int fid = tid + i * 256;
                int n = fid >> 3, kc = (fid & 7) * 4;
                cpa16(sb + (uint32_t)((buf * BSZ + n * AS_LD + kc) << 2),
                      Bb + (size_t)(n0 + n) * ldb + kbase + kc);
            }
        } else {
            #pragma unroll
            for (int i = 0; i < 4; i++) {
                int fid = tid + i * 256;
                int k = fid >> 5, nc = (fid & 31) * 4;
                cpa16(sb + (uint32_t)((buf * BSZ + k * BSN_LD + nc) << 2),
                      Bb + (size_t)(kbase + k) * ldb + n0 + nc);
            }
        }
        asm volatile("cp.async.commit_group;\n");
    };

    load_tile(0, 0);

    for (int it = 0; it < nIter; it++) {
        const int buf = it & 1;
        if (it + 1 < nIter) {
            load_tile(it + 1, buf ^ 1);
            asm volatile("cp.async.wait_group 1;\n");
        } else {
            asm volatile("cp.async.wait_group 0;\n");
        }
        __syncthreads();

        const float* Asb = As + buf * ASZ;
        const float* Bsb = Bs + buf * BSZ;
        #pragma unroll
        for (int kk = 0; kk < 32; kk += 8) {
            unsigned a[4][4], bfr[4][2];
            #pragma unroll
            for (int mi = 0; mi < 4; mi++) {
                const float* ap = Asb + (wm + mi * 16 + g) * AS_LD + kk + tg;
                a[mi][0] = __float_as_uint(ap[0]);
                a[mi][2] = __float_as_uint(ap[4]);
                a[mi][1] = __float_as_uint(ap[8 * AS_LD]);
                a[mi][3] = __float_as_uint(ap[8 * AS_LD + 4]);
            }
            #pragma unroll
            for (int ni = 0; ni < 4; ni++) {
                if (TRANSB) {
                    const float* bp = Bsb + (wn + ni * 8 + g) * AS_LD + kk + tg;
                    bfr[ni][0] = __float_as_uint(bp[0]);
                    bfr[ni][1] = __float_as_uint(bp[4]);
                } else {
                    bfr[ni][0] = __float_as_uint(Bsb[(kk + tg) * BSN_LD + wn + ni * 8 + g]);
                    bfr[ni][1] = __float_as_uint(Bsb[(kk + 4 + tg) * BSN_LD + wn + ni * 8 + g]);
                }
            }
            #pragma unroll
            for (int mi = 0; mi < 4; mi++)
                #pragma unroll
                for (int ni = 0; ni < 4; ni++)
                    mma_tf32(acc[mi][ni], a[mi], bfr[ni]);
        }
        __syncthreads();
    }

    // ---- epilogue ----
    #pragma unroll
    for (int mi = 0; mi < 4; mi++) {
        const int r0 = m0 + wm + mi * 16 + g;
        const int r1 = r0 + 8;
        #pragma unroll
        for (int ni = 0; ni < 4; ni++) {
            const int cc = n0 + wn + ni * 8 + 2 * tg;
            float v00 = acc[mi][ni][0], v01 = acc[mi][ni][1];
            float v10 = acc[mi][ni][2], v11 = acc[mi][ni][3];
            if (EPI == 1) { v00 *= scale; v01 *= scale; v10 *= scale; v11 *= scale; }
            if (EPI >= 2) {
                float bz0 = (cc < N) ? bias[cc] : 0.f;
                float bz1 = (cc + 1 < N) ? bias[cc + 1] : 0.f;
                v00 += bz0; v01 += bz1; v10 += bz0; v11 += bz1;
            }
            if (EPI == 2) {
                v00 = 0.5f * v00 * (1.0f + erff(v00 * 0.70710678118654752f));
                v01 = 0.5f * v01 * (1.0f + erff(v01 * 0.70710678118654752f));
                v10 = 0.5f * v10 * (1.0f + erff(v10 * 0.70710678118654752f));
                v11 = 0.5f * v11 * (1.0f + erff(v11 * 0.70710678118654752f));
            }
            if (EPI == 3) {
                if (cc < N) {
                    v00 += R[(size_t)r0 * ldc + cc];
                    v10 += R[(size_t)r1 * ldc + cc];
                }
                if (cc + 1 < N) {
                    v01 += R[(size_t)r0 * ldc + cc + 1];
                    v11 += R[(size_t)r1 * ldc + cc + 1];
                }
            }
            if (cc < N) {
                Cb[(size_t)r0 * ldc + cc] = v00;
                Cb[(size_t)r1 * ldc + cc] = v10;
            }
            if (cc + 1 < N) {
                Cb[(size_t)r0 * ldc + cc + 1] = v01;
                Cb[(size_t)r1 * ldc + cc + 1] = v11;
            }
        }
    }
}

// ---------------- host-side launch helpers ----------------
template <int EPI>
static void launch_gemm(const float* A, const float* Bm, const float* bias,
                        const float* R, float* C,
                        int M, int N, int K, int lda, int ldb, int ldc) {
    constexpr int ASZ = 128 * AS_LD;
    constexpr int BSZ = 32 * BSN_LD;
    const int smemBytes = (2 * ASZ + 2 * BSZ) * 4;
    cudaFuncSetAttribute(mma_gemm<EPI, 0>,
                         cudaFuncAttributeMaxDynamicSharedMemorySize, smemBytes);
    dim3 grid((N + 127) / 128, M / 128, 1), blk(256);
    mma_gemm<EPI, 0><<<grid, blk, smemBytes>>>(A, Bm, bias, R, C, 1.f,
                                               M, N, K, lda, ldb, ldc);
}

static void launch_flash(const float* Q, const float* KV, const float* VM, float* AO,
                         const int* eff, const int* usr, int Lk, int self_mode) {
    const int smemBytes = (FQ*QLD + 2*FK*KLD + 2*FK*VLD + FQ*PLD) * 4;
    cudaFuncSetAttribute(flash_kernel,
                         cudaFuncAttributeMaxDynamicSharedMemorySize, smemBytes);
    dim3 grid(L_ / FQ, B_ * H_), blk(256);
    flash_kernel<<<grid, blk, smemBytes>>>(Q, KV, VM, AO, eff, usr, Lk, self_mode);
}

extern "C" void kernel_launch(void* const* d_in, const int* in_sizes, int n_in,
                              void* d_out, int out_size) {
    const float* x    = (const float*)d_in[0];
    const float* c    = (const float*)d_in[1];
    const int*   eff  = (const int*)  d_in[2];
    const int*   usr  = (const int*)  d_in[3];
    const float* Wq1  = (const float*)d_in[4];
    const float* Wkv1 = (const float*)d_in[5];
    const float* Wo1  = (const float*)d_in[6];
    const float* bo1  = (const float*)d_in[7];
    const float* Wq2  = (const float*)d_in[8];
    const float* Wkv2 = (const float*)d_in[9];
    const float* Wo2  = (const float*)d_in[10];
    const float* bo2  = (const float*)d_in[11];
    const float* g1   = (const float*)d_in[12];
    const float* b1   = (const float*)d_in[13];
    const float* g2   = (const float*)d_in[14];
    const float* b2   = (const float*)d_in[15];
    const float* g4   = (const float*)d_in[16];
    const float* b4   = (const float*)d_in[17];
    const float* gc   = (const float*)d_in[18];
    const float* bc   = (const float*)d_in[19];
    const float* Wf1  = (const float*)d_in[20];
    const float* bf1  = (const float*)d_in[21];
    const float* Wf2  = (const float*)d_in[22];
    const float* bf2  = (const float*)d_in[23];
    float* out = (float*)d_out;

    float *XN, *CN, *Q, *KV, *AO, *X2, *Hf, *VM;
    cudaGetSymbolAddress((void**)&XN, g_XN);
    cudaGetSymbolAddress((void**)&CN, g_CN);
    cudaGetSymbolAddress((void**)&Q,  g_Q);
    cudaGetSymbolAddress((void**)&KV, g_KV);
    cudaGetSymbolAddress((void**)&AO, g_AO);
    cudaGetSymbolAddress((void**)&X2, g_X2);
    cudaGetSymbolAddress((void**)&Hf, g_H);
    cudaGetSymbolAddress((void**)&VM, g_VM);

    // ---------- self-attention ----------
    ln_kernel<<<NTX, 256>>>(x, g1, b1, XN);
    launch_gemm<0>(XN, Wq1,  nullptr, nullptr, Q,  NTX, C_,   C_, C_, C_,   C_);
    launch_gemm<0>(XN, Wkv1, nullptr, nullptr, KV, NTX, 2*C_, C_, C_, 2*C_, 2*C_);
    vmean_kernel<<<B_*H_, 96>>>(KV, VM, L_);
    launch_flash(Q, KV, VM, AO, eff, usr, L_, 1);
    launch_gemm<3>(AO, Wo1, bo1, x, X2, NTX, C_, C_, C_, C_, C_);

    // ---------- cross-attention ----------
    ln_kernel<<<NTX, 256>>>(X2, g2, b2, XN);
    ln_kernel<<<NTC, 256>>>(c,  gc, bc, CN);
    launch_gemm<0>(XN, Wq2,  nullptr, nullptr, Q,  NTX, C_,   C_, C_, C_,   C_);
    launch_gemm<0>(CN, Wkv2, nullptr, nullptr, KV, NTC, 2*C_, C_, C_, 2*C_, 2*C_);
    vmean_kernel<<<B_*H_, 96>>>(KV, VM, S_);
    launch_flash(Q, KV, VM, AO, eff, usr, S_, 0);
    launch_gemm<3>(AO, Wo2, bo2, X2, X2, NTX, C_, C_, C_, C_, C_);

    // ---------- FFN ----------
    ln_kernel<<<NTX, 256>>>(X2, g4, b4, XN);
    launch_gemm<2>(XN, Wf1, bf1, nullptr, Hf, NTX, F_, C_, C_, F_, F_);
    launch_gemm<3>(Hf, Wf2, bf2, X2, out, NTX, C_, F_, F_, C_, C_);
}

// round 7
// speedup vs baseline: 4.7188x; 1.0455x over previous
#include <cuda_runtime.h>
#include <cuda_bf16.h>
#include <math.h>
#include <stdint.h>

#define B_  8
#define L_  1024
#define S_  512
#define C_  768
#define H_  8
#define D_  96
#define F_  3072
#define NTX (B_*L_)
#define NTC (B_*S_)
#define VSPLIT 16

// ---------------- scratch ----------------
__device__ float g_XN[(size_t)NTX*C_ + 64];
__device__ float g_CN[(size_t)NTC*C_ + 64];
__device__ float g_Q [(size_t)NTX*C_ + 64];
__device__ float g_KV[(size_t)NTX*2*C_ + 64];
__device__ float g_AO[(size_t)NTX*C_ + 64];
__device__ float g_X2[(size_t)NTX*C_ + 64];
__device__ float g_H [(size_t)NTX*F_ + 64];
__device__ float g_VM[(size_t)B_*C_ + 64];
__device__ float g_VMp[(size_t)B_*VSPLIT*C_ + 64];

// ---------------- reductions ----------------
__device__ __forceinline__ float blockReduceSum(float v) {
    __shared__ float sh[32];
    __syncthreads();
    int lane = threadIdx.x & 31, wid = threadIdx.x >> 5;
    #pragma unroll
    for (int o = 16; o; o >>= 1) v += __shfl_down_sync(0xffffffffu, v, o);
    if (lane == 0) sh[wid] = v;
    __syncthreads();
    int nw = blockDim.x >> 5;
    v = (threadIdx.x < nw) ? sh[threadIdx.x] : 0.0f;
    if (wid == 0) {
        #pragma unroll
        for (int o = 16; o; o >>= 1) v += __shfl_down_sync(0xffffffffu, v, o);
        if (lane == 0) sh[0] = v;
    }
    __syncthreads();
    return sh[0];
}

// ---------------- layernorm ----------------
__global__ void ln_kernel(const float* __restrict__ X,
                          const float* __restrict__ g, const float* __restrict__ b,
                          float* __restrict__ Y) {
    const int row = blockIdx.x;
    const float* x = X + (size_t)row * C_;
    float s = 0.f, s2 = 0.f;
    for (int j = threadIdx.x; j < C_; j += blockDim.x) {
        float v = x[j];
        s += v; s2 += v * v;
    }
    s  = blockReduceSum(s);
    s2 = blockReduceSum(s2);
    const float mean = s * (1.0f / C_);
    const float var  = s2 * (1.0f / C_) - mean * mean;
    const float inv  = rsqrtf(var + 1e-5f);
    float* y = Y + (size_t)row * C_;
    for (int j = threadIdx.x; j < C_; j += blockDim.x)
        y[j] = (x[j] - mean) * inv * g[j] + b[j];
}

// ---------------- cp.async helpers ----------------
__device__ __forceinline__ void cpa16(uint32_t dst, const float* src) {
    asm volatile("cp.async.cg.shared.global [%0], [%1], 16;\n" :: "r"(dst), "l"(src));
}

__device__ __forceinline__ void mma_tf32(float* d, const unsigned* a, const unsigned* b) {
    asm volatile(
        "mma.sync.aligned.m16n8k8.row.col.f32.tf32.tf32.f32 "
        "{%0,%1,%2,%3}, {%4,%5,%6,%7}, {%8,%9}, {%0,%1,%2,%3};"
        : "+f"(d[0]), "+f"(d[1]), "+f"(d[2]), "+f"(d[3])
        : "r"(a[0]), "r"(a[1]), "r"(a[2]), "r"(a[3]), "r"(b[0]), "r"(b[1]));
}

// ---------------- V column mean (2-phase, parallel) ----------------
// phase1: grid (B, VSPLIT), block C_: partial sums, coalesced full-row reads
__global__ void vmean1_kernel(const float* __restrict__ KVg, float* __restrict__ VMp, int Lk) {
    const int b = blockIdx.x, s = blockIdx.y, col = threadIdx.x;
    const int rows = Lk / VSPLIT;
    const float* Vb = KVg + (size_t)b * Lk * (2*C_) + C_ + col;
    float sum = 0.f;
    const int j0 = s * rows;
    #pragma unroll 4
    for (int j = j0; j < j0 + rows; j++) sum += Vb[(size_t)j * (2*C_)];
    VMp[((size_t)b * VSPLIT + s) * C_ + col] = sum;
}
// phase2: grid B, block C_
__global__ void vmean2_kernel(const float* __restrict__ VMp, float* __restrict__ VM, int Lk) {
    const int b = blockIdx.x, col = threadIdx.x;
    float sum = 0.f;
    #pragma unroll
    for (int s = 0; s < VSPLIT; s++) sum += VMp[((size_t)b * VSPLIT + s) * C_ + col];
    VM[(size_t)b * C_ + col] = sum / (float)Lk;
}

// ---------------- flash attention (tf32 mma, online softmax) ----------------
#define FQ 128
#define FK 64
#define QLD 100
#define KLD 100
#define VLD 104
#define PLD 68

__global__ __launch_bounds__(256)
void flash_kernel(const float* __restrict__ Qg, const float* __restrict__ KVg,
                  const float* __restrict__ VM, float* __restrict__ AO,
                  const int* __restrict__ eff, const int* __restrict__ usp,
                  int Lk, int self_mode) {
    extern __shared__ float sm[];
    float* Qs = sm;                       // FQ x QLD
    float* Ks = Qs + FQ*QLD;              // 2 x FK x KLD
    float* Vs = Ks + 2*FK*KLD;            // 2 x FK x VLD
    float* Ps = Vs + 2*FK*VLD;            // FQ x PLD

    const int bh = blockIdx.y, b = bh >> 3, h = bh & 7;
    const int i0 = blockIdx.x * FQ;
    const int e  = eff[b];
    const int el = e * usp[0];
    const int jl = self_mode ? el : e;

    const int tid = threadIdx.x, lane = tid & 31, warp = tid >> 5;
    const int g = lane >> 2, tg = lane & 3;
    const int wm = warp * 16;

    const float* Qrow = Qg + ((size_t)b * L_ + i0) * C_ + h * D_;
    const float* Kb   = KVg + (size_t)b * Lk * (2*C_) + h * D_;
    const float* Vb   = Kb + C_;
    float*       AOb  = AO + ((size_t)b * L_ + i0) * C_ + h * D_;

    // fill masked rows (i >= el) with V-mean
    const int rm0 = (el > i0) ? ((el - i0 < FQ) ? (el - i0) : FQ) : 0;
    if (rm0 < FQ) {
        const float* vm = VM + (size_t)b * C_ + h * D_;
        for (int idx = tid; idx < (FQ - rm0) * D_; idx += 256) {
            int r = rm0 + idx / D_, cc = idx % D_;
            AOb[(size_t)r * C_ + cc] = vm[cc];
        }
    }
    if (rm0 == 0) return;   // whole block masked

    // async-load Q tile
    {
        const uint32_t sq = (uint32_t)__cvta_generic_to_shared(Qs);
        for (int t = tid; t < FQ * 24; t += 256) {
            int r = t / 24, cq = (t % 24) * 4;
            cpa16(sq + (uint32_t)((r * QLD + cq) << 2), Qrow + (size_t)r * C_ + cq);
        }
        asm volatile("cp.async.commit_group;\n");
    }

    const uint32_t sk = (uint32_t)__cvta_generic_to_shared(Ks);
    const uint32_t sv = (uint32_t)__cvta_generic_to_shared(Vs);
    const int nkt = (jl + FK - 1) / FK;

    auto load_kv = [&](int t, int buf) {
        const int j0 = t * FK;
        for (int i = tid; i < FK * 24; i += 256) {
            int r = i / 24, cq = (i % 24) * 4;
            const size_t off = (size_t)(j0 + r) * (2*C_) + cq;
            cpa16(sk + (uint32_t)((buf * FK * KLD + r * KLD + cq) << 2), Kb + off);
            cpa16(sv + (uint32_t)((buf * FK * VLD + r * VLD + cq) << 2), Vb + off);
        }
        asm volatile("cp.async.commit_group;\n");
    };

    load_kv(0, 0);
    asm volatile("cp.async.wait_group 0;\n");
    __syncthreads();

    // Q fragments (pre-scaled by 1/sqrt(d))
    const float scale = rsqrtf((float)D_);
    unsigned qf[12][4];
    #pragma unroll
    for (int kk = 0; kk < 12; kk++) {
        qf[kk][0] = __float_as_uint(Qs[(wm+g  )*QLD + kk*8 + tg    ] * scale);
        qf[kk][1] = __float_as_uint(Qs[(wm+g+8)*QLD + kk*8 + tg    ] * scale);
        qf[kk][2] = __float_as_uint(Qs[(wm+g  )*QLD + kk*8 + tg + 4] * scale);
        qf[kk][3] = __float_as_uint(Qs[(wm+g+8)*QLD + kk*8 + tg + 4] * scale);
    }

    float Oacc[12][4] = {};
    float m0 = -1e30f, m1 = -1e30f, l0 = 0.f, l1 = 0.f;

    for (int t = 0; t < nkt; t++) {
        const int buf = t & 1;
        if (t + 1 < nkt) {
            load_kv(t + 1, buf ^ 1);
            asm volatile("cp.async.wait_group 1;\n");
        } else {
            asm volatile("cp.async.wait_group 0;\n");
        }
        __syncthreads();

        const float* Kst = Ks + buf * FK * KLD;
        const float* Vst = Vs + buf * FK * VLD;

        // ---- S = Q @ K^T (scaled) ----
        float sacc[8][4] = {};
        #pragma unroll
        for (int kk = 0; kk < 12; kk++) {
            unsigned bf[8][2];
            #pragma unroll
            for (int ni = 0; ni < 8; ni++) {
                bf[ni][0] = __float_as_uint(Kst[(ni*8+g)*KLD + kk*8 + tg    ]);
                bf[ni][1] = __float_as_uint(Kst[(ni*8+g)*KLD + kk*8 + tg + 4]);
            }
            #pragma unroll
            for (int ni = 0; ni < 8; ni++)
                mma_tf32(sacc[ni], qf[kk], bf[ni]);
        }

        // ---- mask ----
        const int jb = t * FK + 2*tg;
        #pragma unroll
        for (int ni = 0; ni < 8; ni++) {
            const int j = jb + ni*8;
            if (j     >= jl) { sacc[ni][0] = -1e30f; sacc[ni][2] = -1e30f; }
            if (j + 1 >= jl) { sacc[ni][1] = -1e30f; sacc[ni][3] = -1e30f; }
        }

        // ---- online softmax (rows g, g+8) ----
        float mx0 = -1e30f, mx1 = -1e30f;
        #pragma unroll
        for (int ni = 0; ni < 8; ni++) {
            mx0 = fmaxf(mx0, fmaxf(sacc[ni][0], sacc[ni][1]));
            mx1 = fmaxf(mx1, fmaxf(sacc[ni][2], sacc[ni][3]));
        }
        mx0 = fmaxf(mx0, __shfl_xor_sync(0xffffffffu, mx0, 1));
        mx0 = fmaxf(mx0, __shfl_xor_sync(0xffffffffu, mx0, 2));
        mx1 = fmaxf(mx1, __shfl_xor_sync(0xffffffffu, mx1, 1));
        mx1 = fmaxf(mx1, __shfl_xor_sync(0xffffffffu, mx1, 2));
        const float nm0 = fmaxf(m0, mx0), nm1 = fmaxf(m1, mx1);
        const float a0 = __expf(m0 - nm0), a1 = __expf(m1 - nm1);
        float rs0 = 0.f, rs1 = 0.f;
        #pragma unroll
        for (int ni = 0; ni < 8; ni++) {
            sacc[ni][0] = __expf(sacc[ni][0] - nm0);
            sacc[ni][1] = __expf(sacc[ni][1] - nm0);
            sacc[ni][2] = __expf(sacc[ni][2] - nm1);
            sacc[ni][3] = __expf(sacc[ni][3] - nm1);
            rs0 += sacc[ni][0] + sacc[ni][1];
            rs1 += sacc[ni][2] + sacc[ni][3];
        }
        rs0 += __shfl_xor_sync(0xffffffffu, rs0, 1);
        rs0 += __shfl_xor_sync(0xffffffffu, rs0, 2);
        rs1 += __shfl_xor_sync(0xffffffffu, rs1, 1);
        rs1 += __shfl_xor_sync(0xffffffffu, rs1, 2);
        l0 = l0 * a0 + rs0;
        l1 = l1 * a1 + rs1;
        m0 = nm0; m1 = nm1;
        #pragma unroll
        for (int nj = 0; nj < 12; nj++) {
            Oacc[nj][0] *= a0; Oacc[nj][1] *= a0;
            Oacc[nj][2] *= a1; Oacc[nj][3] *= a1;
        }

        // ---- stage P (per-warp-private rows) ----
        #pragma unroll
        for (int ni = 0; ni < 8; ni++) {
            *(float2*)&Ps[(wm+g  )*PLD + ni*8 + 2*tg] = make_float2(sacc[ni][0], sacc[ni][1]);
            *(float2*)&Ps[(wm+g+8)*PLD + ni*8 + 2*tg] = make_float2(sacc[ni][2], sacc[ni][3]);
        }
        __syncwarp();

        // ---- O += P @ V ----
        #pragma unroll
        for (int kk = 0; kk < 8; kk++) {
            unsigned af[4];
            af[0] = __float_as_uint(Ps[(wm+g  )*PLD + kk*8 + tg    ]);
            af[1] = __float_as_uint(Ps[(wm+g+8)*PLD + kk*8 + tg    ]);
            af[2] = __float_as_uint(Ps[(wm+g  )*PLD + kk*8 + tg + 4]);
            af[3] = __float_as_uint(Ps[(wm+g+8)*PLD + kk*8 + tg + 4]);
            #pragma unroll
            for (int nj = 0; nj < 12; nj++) {
                unsigned bv[2];
                bv[0] = __float_as_uint(Vst[(kk*8+tg  )*VLD + nj*8 + g]);
                bv[1] = __float_as_uint(Vst[(kk*8+tg+4)*VLD + nj*8 + g]);
                mma_tf32(Oacc[nj], af, bv);
            }
        }
        __syncthreads();   // protect K/V buffers before next prefetch
    }

    // ---- epilogue ----
    const float inv0 = 1.f / l0, inv1 = 1.f / l1;
    #pragma unroll
    for (int nj = 0; nj < 12; nj++) {
        const int ccol = nj*8 + 2*tg;
        if (i0 + wm + g < el)
            *(float2*)&AOb[(size_t)(wm+g  )*C_ + ccol] =
                make_float2(Oacc[nj][0]*inv0, Oacc[nj][1]*inv0);
        if (i0 + wm + g + 8 < el)
            *(float2*)&AOb[(size_t)(wm+g+8)*C_ + ccol] =
                make_float2(Oacc[nj][2]*inv1, Oacc[nj][3]*inv1);
    }
}

// ---------------- tf32 GEMM, 3-stage cp.async pipeline ----------------
#define AS_LD 36
#define BSN_LD 136
#define NSTAGE 3

template <int EPI>
__global__ __launch_bounds__(256, 2)
void mma_gemm(const float* __restrict__ A, const float* __restrict__ Bm,
              const float* __restrict__ bias, const float* __restrict__ R,
              float* __restrict__ Cc,
              int M, int N, int K, int lda, int ldb, int ldc) {
    extern __shared__ float smem[];
    constexpr int ASZ = 128 * AS_LD;
    constexpr int BSZ = 32 * BSN_LD;
    float* As = smem;
    float* Bs = smem + NSTAGE * ASZ;
    const uint32_t sa = (uint32_t)__cvta_generic_to_shared(As);
    const uint32_t sb = (uint32_t)__cvta_generic_to_shared(Bs);

    const int m0 = blockIdx.y * 128, n0 = blockIdx.x * 128;
    const int tid = threadIdx.x, lane = tid & 31, warp = tid >> 5;
    const int wm = (warp & 1) * 64;
    const int wn = (warp >> 1) * 32;
    const int g = lane >> 2, tg = lane & 3;

    float acc[4][4][4] = {};
    const int nIter = K >> 5;

    auto load_tile = [&](int it, int buf) {
        const int kbase = it * 32;
        #pragma unroll
        for (int i = 0; i < 4; i++) {
            int fid = tid + i * 256;
            int m = fid >> 3, kc = (fid & 7) * 4;
            cpa16(sa + (uint32_t)((buf * ASZ + m * AS_LD + kc) << 2),
                  A + (size_t)(m0 + m) * lda + kbase + kc);
        }
        #pragma unroll
        for (int i = 0; i < 4; i++) {
            int fid = tid + i * 256;
            int k = fid >> 5, nc = (fid & 31) * 4;
            cpa16(sb + (uint32_t)((buf * BSZ + k * BSN_LD + nc) << 2),
                  Bm + (size_t)(kbase + k) * ldb + n0 + nc);
        }
        asm volatile("cp.async.commit_group;\n");
    };

    load_tile(0, 0);
    if (nIter > 1) load_tile(1, 1);

    for (int it = 0; it < nIter; it++) {
        const int buf = it % NSTAGE;
        if (it + 2 < nIter) {
            load_tile(it + 2, (it + 2) % NSTAGE);
            asm volatile("cp.async.wait_group 2;\n");
        } else if (it + 1 < nIter) {
            asm volatile("cp.async.wait_group 1;\n");
        } else {
            asm volatile("cp.async.wait_group 0;\n");
        }
        __syncthreads();

        const float* Asb = As + buf * ASZ;
        const float* Bsb = Bs + buf * BSZ;
        #pragma unroll
        for (int kk = 0; kk < 32; kk += 8) {
            unsigned a[4][4], bfr[4][2];
            #pragma unroll
            for (int mi = 0; mi < 4; mi++) {
                const float* ap = Asb + (wm + mi * 16 + g) * AS_LD + kk + tg;
                a[mi][0] = __float_as_uint(ap[0]);
                a[mi][2] = __float_as_uint(ap[4]);
                a[mi][1] = __float_as_uint(ap[8 * AS_LD]);
                a[mi][3] = __float_as_uint(ap[8 * AS_LD + 4]);
            }
            #pragma unroll
            for (int ni = 0; ni < 4; ni++) {
                bfr[ni][0] = __float_as_uint(Bsb[(kk + tg) * BSN_LD + wn + ni * 8 + g]);
                bfr[ni][1] = __float_as_uint(Bsb[(kk + 4 + tg) * BSN_LD + wn + ni * 8 + g]);
            }
            #pragma unroll
            for (int mi = 0; mi < 4; mi++)
                #pragma unroll
                for (int ni = 0; ni < 4; ni++)
                    mma_tf32(acc[mi][ni], a[mi], bfr[ni]);
        }
        __syncthreads();
    }

    // ---- epilogue ----
    #pragma unroll
    for (int mi = 0; mi < 4; mi++) {
        const int r0 = m0 + wm + mi * 16 + g;
        const int r1 = r0 + 8;
        #pragma unroll
        for (int ni = 0; ni < 4; ni++) {
            const int cc = n0 + wn + ni * 8 + 2 * tg;
            float v00 = acc[mi][ni][0], v01 = acc[mi][ni][1];
            float v10 = acc[mi][ni][2], v11 = acc[mi][ni][3];
            if (EPI >= 2) {
                float bz0 = (cc < N) ? bias[cc] : 0.f;
                float bz1 = (cc + 1 < N) ? bias[cc + 1] : 0.f;
                v00 += bz0; v01 += bz1; v10 += bz0; v11 += bz1;
            }
            if (EPI == 2) {
                v00 = 0.5f * v00 * (1.0f + erff(v00 * 0.70710678118654752f));
                v01 = 0.5f * v01 * (1.0f + erff(v01 * 0.70710678118654752f));
                v10 = 0.5f * v10 * (1.0f + erff(v10 * 0.70710678118654752f));
                v11 = 0.5f * v11 * (1.0f + erff(v11 * 0.70710678118654752f));
            }
            if (EPI == 3) {
                if (cc < N) {
                    v00 += R[(size_t)r0 * ldc + cc];
                    v10 += R[(size_t)r1 * ldc + cc];
                }
                if (cc + 1 < N) {
                    v01 += R[(size_t)r0 * ldc + cc + 1];
                    v11 += R[(size_t)r1 * ldc + cc + 1];
                }
            }
            if (cc < N) {
                Cb_store: ;
                Cc[(size_t)r0 * ldc + cc] = v00;
                Cc[(size_t)r1 * ldc + cc] = v10;
            }
            if (cc + 1 < N) {
                Cc[(size_t)r0 * ldc + cc + 1] = v01;
                Cc[(size_t)r1 * ldc + cc + 1] = v11;
            }
        }
    }
}

// ---------------- host-side launch helpers ----------------
template <int EPI>
static void launch_gemm(const float* A, const float* Bm, const float* bias,
                        const float* R, float* C,
                        int M, int N, int K, int lda, int ldb, int ldc) {
    constexpr int ASZ = 128 * AS_LD;
    constexpr int BSZ = 32 * BSN_LD;
    const int smemBytes = NSTAGE * (ASZ + BSZ) * 4;
    cudaFuncSetAttribute(mma_gemm<EPI>,
                         cudaFuncAttributeMaxDynamicSharedMemorySize, smemBytes);
    dim3 grid((N + 127) / 128, M / 128, 1), blk(256);
    mma_gemm<EPI><<<grid, blk, smemBytes>>>(A, Bm, bias, R, C, M, N, K, lda, ldb, ldc);
}

static void launch_flash(const float* Q, const float* KV, const float* VM, float* AO,
                         const int* eff, const int* usr, int Lk, int self_mode) {
    const int smemBytes = (FQ*QLD + 2*FK*KLD + 2*FK*VLD + FQ*PLD) * 4;
    cudaFuncSetAttribute(flash_kernel,
                         cudaFuncAttributeMaxDynamicSharedMemorySize, smemBytes);
    dim3 grid(L_ / FQ, B_ * H_), blk(256);
    flash_kernel<<<grid, blk, smemBytes>>>(Q, KV, VM, AO, eff, usr, Lk, self_mode);
}

extern "C" void kernel_launch(void* const* d_in, const int* in_sizes, int n_in,
                              void* d_out, int out_size) {
    const float* x    = (const float*)d_in[0];
    const float* c    = (const float*)d_in[1];
    const int*   eff  = (const int*)  d_in[2];
    const int*   usr  = (const int*)  d_in[3];
    const float* Wq1  = (const float*)d_in[4];
    const float* Wkv1 = (const float*)d_in[5];
    const float* Wo1  = (const float*)d_in[6];
    const float* bo1  = (const float*)d_in[7];
    const float* Wq2  = (const float*)d_in[8];
    const float* Wkv2 = (const float*)d_in[9];
    const float* Wo2  = (const float*)d_in[10];
    const float* bo2  = (const float*)d_in[11];
    const float* g1   = (const float*)d_in[12];
    const float* b1   = (const float*)d_in[13];
    const float* g2   = (const float*)d_in[14];
    const float* b2   = (const float*)d_in[15];
    const float* g4   = (const float*)d_in[16];
    const float* b4   = (const float*)d_in[17];
    const float* gc   = (const float*)d_in[18];
    const float* bc   = (const float*)d_in[19];
    const float* Wf1  = (const float*)d_in[20];
    const float* bf1  = (const float*)d_in[21];
    const float* Wf2  = (const float*)d_in[22];
    const float* bf2  = (const float*)d_in[23];
    float* out = (float*)d_out;

    float *XN, *CN, *Q, *KV, *AO, *X2, *Hf, *VM, *VMp;
    cudaGetSymbolAddress((void**)&XN, g_XN);
    cudaGetSymbolAddress((void**)&CN, g_CN);
    cudaGetSymbolAddress((void**)&Q,  g_Q);
    cudaGetSymbolAddress((void**)&KV, g_KV);
    cudaGetSymbolAddress((void**)&AO, g_AO);
    cudaGetSymbolAddress((void**)&X2, g_X2);
    cudaGetSymbolAddress((void**)&Hf, g_H);
    cudaGetSymbolAddress((void**)&VM, g_VM);
    cudaGetSymbolAddress((void**)&VMp, g_VMp);

    // ---------- self-attention ----------
    ln_kernel<<<NTX, 256>>>(x, g1, b1, XN);
    launch_gemm<0>(XN, Wq1,  nullptr, nullptr, Q,  NTX, C_,   C_, C_, C_,   C_);
    launch_gemm<0>(XN, Wkv1, nullptr, nullptr, KV, NTX, 2*C_, C_, C_, 2*C_, 2*C_);
    vmean1_kernel<<<dim3(B_, VSPLIT), C_>>>(KV, VMp, L_);
    vmean2_kernel<<<B_, C_>>>(VMp, VM, L_);
    launch_flash(Q, KV, VM, AO, eff, usr, L_, 1);
    launch_gemm<3>(AO, Wo1, bo1, x, X2, NTX, C_, C_, C_, C_, C_);

    // ---------- cross-attention ----------
    ln_kernel<<<NTX, 256>>>(X2, g2, b2, XN);
    ln_kernel<<<NTC, 256>>>(c,  gc, bc, CN);
    launch_gemm<0>(XN, Wq2,  nullptr, nullptr, Q,  NTX, C_,   C_, C_, C_,   C_);
    launch_gemm<0>(CN, Wkv2, nullptr, nullptr, KV, NTC, 2*C_, C_, C_, 2*C_, 2*C_);
    vmean1_kernel<<<dim3(B_, VSPLIT), C_>>>(KV, VMp, S_);
    vmean2_kernel<<<B_, C_>>>(VMp, VM, S_);
    launch_flash(Q, KV, VM, AO, eff, usr, S_, 0);
    launch_gemm<3>(AO, Wo2, bo2, X2, X2, NTX, C_, C_, C_, C_, C_);

    // ---------- FFN ----------
    ln_kernel<<<NTX, 256>>>(X2, g4, b4, XN);
    launch_gemm<2>(XN, Wf1, bf1, nullptr, Hf, NTX, F_, C_, C_, F_, F_);
    launch_gemm<3>(Hf, Wf2, bf2, X2, out, NTX, C_, F_, F_, C_, C_);
}

// round 8
// speedup vs baseline: 5.5335x; 1.1726x over previous
#include <cuda_runtime.h>
#include <cuda_bf16.h>
#include <math.h>
#include <stdint.h>

#define B_  8
#define L_  1024
#define S_  512
#define C_  768
#define H_  8
#define D_  96
#define F_  3072
#define NTX (B_*L_)
#define NTC (B_*S_)
#define RS 8

// ---------------- scratch ----------------
__device__ float g_XN[(size_t)NTX*C_ + 64];
__device__ float g_CN[(size_t)NTC*C_ + 64];
__device__ float g_Q [(size_t)NTX*C_ + 64];
__device__ float g_KV[(size_t)NTX*2*C_ + 64];
__device__ float g_AO[(size_t)NTX*C_ + 64];
__device__ float g_X2[(size_t)NTX*C_ + 64];
__device__ float g_H [(size_t)NTX*F_ + 64];
__device__ float g_VM[(size_t)B_*C_ + 64];
__device__ float g_RMp[(size_t)B_*RS*C_ + 64];

// ---------------- reductions ----------------
__device__ __forceinline__ float blockReduceSum(float v) {
    __shared__ float sh[32];
    __syncthreads();
    int lane = threadIdx.x & 31, wid = threadIdx.x >> 5;
    #pragma unroll
    for (int o = 16; o; o >>= 1) v += __shfl_down_sync(0xffffffffu, v, o);
    if (lane == 0) sh[wid] = v;
    __syncthreads();
    int nw = blockDim.x >> 5;
    v = (threadIdx.x < nw) ? sh[threadIdx.x] : 0.0f;
    if (wid == 0) {
        #pragma unroll
        for (int o = 16; o; o >>= 1) v += __shfl_down_sync(0xffffffffu, v, o);
        if (lane == 0) sh[0] = v;
    }
    __syncthreads();
    return sh[0];
}

// ---------------- layernorm (float4, row held in registers) ----------------
__global__ void ln_kernel(const float* __restrict__ X,
                          const float* __restrict__ g, const float* __restrict__ b,
                          float* __restrict__ Y) {
    const int row = blockIdx.x, tid = threadIdx.x;
    const float4* x4 = (const float4*)(X + (size_t)row * C_);
    float4 v = make_float4(0.f, 0.f, 0.f, 0.f);
    float s = 0.f, s2 = 0.f;
    if (tid < 192) {
        v = x4[tid];
        s  = v.x + v.y + v.z + v.w;
        s2 = v.x*v.x + v.y*v.y + v.z*v.z + v.w*v.w;
    }
    s  = blockReduceSum(s);
    s2 = blockReduceSum(s2);
    const float mean = s * (1.0f / C_);
    const float var  = s2 * (1.0f / C_) - mean * mean;
    const float inv  = rsqrtf(var + 1e-5f);
    if (tid < 192) {
        const float4 gv = ((const float4*)g)[tid];
        const float4 bv = ((const float4*)b)[tid];
        float4 y;
        y.x = (v.x - mean) * inv * gv.x + bv.x;
        y.y = (v.y - mean) * inv * gv.y + bv.y;
        y.z = (v.z - mean) * inv * gv.z + bv.z;
        y.w = (v.w - mean) * inv * gv.w + bv.w;
        ((float4*)(Y + (size_t)row * C_))[tid] = y;
    }
}

// ---------------- cp.async helpers ----------------
__device__ __forceinline__ void cpa16(uint32_t dst, const float* src) {
    asm volatile("cp.async.cg.shared.global [%0], [%1], 16;\n" :: "r"(dst), "l"(src));
}

__device__ __forceinline__ void mma_tf32(float* d, const unsigned* a, const unsigned* b) {
    asm volatile(
        "mma.sync.aligned.m16n8k8.row.col.f32.tf32.tf32.f32 "
        "{%0,%1,%2,%3}, {%4,%5,%6,%7}, {%8,%9}, {%0,%1,%2,%3};"
        : "+f"(d[0]), "+f"(d[1]), "+f"(d[2]), "+f"(d[3])
        : "r"(a[0]), "r"(a[1]), "r"(a[2]), "r"(a[3]), "r"(b[0]), "r"(b[1]));
}

// ---------------- V-mean via rowmean(XN/CN) @ Wv  (linear; exact) ----------------
// phase1: grid (B, RS), block 768: partial column sums of the normalized stream
__global__ void rowmean1_kernel(const float* __restrict__ X, float* __restrict__ part, int Lk) {
    const int b = blockIdx.x, s = blockIdx.y, col = threadIdx.x;
    const int rows = Lk / RS;
    const float* Xb = X + ((size_t)b * Lk + (size_t)s * rows) * C_ + col;
    float sum = 0.f;
    #pragma unroll 4
    for (int j = 0; j < rows; j++) sum += Xb[(size_t)j * C_];
    part[((size_t)b * RS + s) * C_ + col] = sum;
}
// phase2: combine partials -> mean row, then matvec with Wv (row stride 2C_)
__global__ void rowmean2_matvec_kernel(const float* __restrict__ part,
                                       const float* __restrict__ Wv,
                                       float* __restrict__ VM, int Lk) {
    __shared__ float xm[C_];
    const int b = blockIdx.x, n = threadIdx.x;
    float s = 0.f;
    #pragma unroll
    for (int i = 0; i < RS; i++) s += part[((size_t)b * RS + i) * C_ + n];
    xm[n] = s / (float)Lk;
    __syncthreads();
    float acc = 0.f;
    #pragma unroll 8
    for (int k = 0; k < C_; k++) acc = fmaf(xm[k], Wv[(size_t)k * (2*C_) + n], acc);
    VM[(size_t)b * C_ + n] = acc;
}

// ---------------- flash attention (tf32 mma, online softmax) ----------------
#define FQ 128
#define FK 64
#define QLD 100
#define KLD 100
#define VLD 104
#define PLD 68

__global__ __launch_bounds__(256)
void flash_kernel(const float* __restrict__ Qg, const float* __restrict__ KVg,
                  const float* __restrict__ VM, float* __restrict__ AO,
                  const int* __restrict__ eff, const int* __restrict__ usp,
                  int Lk, int self_mode) {
    extern __shared__ float sm[];
    float* Qs = sm;                       // FQ x QLD
    float* Ks = Qs + FQ*QLD;              // 2 x FK x KLD
    float* Vs = Ks + 2*FK*KLD;            // 2 x FK x VLD
    float* Ps = Vs + 2*FK*VLD;            // FQ x PLD

    const int bh = blockIdx.y, b = bh >> 3, h = bh & 7;
    const int i0 = blockIdx.x * FQ;
    const int e  = eff[b];
    const int el = e * usp[0];
    const int jl = self_mode ? el : e;

    const int tid = threadIdx.x, lane = tid & 31, warp = tid >> 5;
    const int g = lane >> 2, tg = lane & 3;
    const int wm = warp * 16;

    const float* Qrow = Qg + ((size_t)b * L_ + i0) * C_ + h * D_;
    const float* Kb   = KVg + (size_t)b * Lk * (2*C_) + h * D_;
    const float* Vb   = Kb + C_;
    float*       AOb  = AO + ((size_t)b * L_ + i0) * C_ + h * D_;

    // fill masked rows (i >= el) with V-mean
    const int rm0 = (el > i0) ? ((el - i0 < FQ) ? (el - i0) : FQ) : 0;
    if (rm0 < FQ) {
        const float* vm = VM + (size_t)b * C_ + h * D_;
        for (int idx = tid; idx < (FQ - rm0) * D_; idx += 256) {
            int r = rm0 + idx / D_, cc = idx % D_;
            AOb[(size_t)r * C_ + cc] = vm[cc];
        }
    }
    if (rm0 == 0) return;   // whole block masked

    // async-load Q tile
    {
        const uint32_t sq = (uint32_t)__cvta_generic_to_shared(Qs);
        for (int t = tid; t < FQ * 24; t += 256) {
            int r = t / 24, cq = (t % 24) * 4;
            cpa16(sq + (uint32_t)((r * QLD + cq) << 2), Qrow + (size_t)r * C_ + cq);
        }
        asm volatile("cp.async.commit_group;\n");
    }

    const uint32_t sk = (uint32_t)__cvta_generic_to_shared(Ks);
    const uint32_t sv = (uint32_t)__cvta_generic_to_shared(Vs);
    const int nkt = (jl + FK - 1) / FK;

    auto load_kv = [&](int t, int buf) {
        const int j0 = t * FK;
        for (int i = tid; i < FK * 24; i += 256) {
            int r = i / 24, cq = (i % 24) * 4;
            const size_t off = (size_t)(j0 + r) * (2*C_) + cq;
            cpa16(sk + (uint32_t)((buf * FK * KLD + r * KLD + cq) << 2), Kb + off);
            cpa16(sv + (uint32_t)((buf * FK * VLD + r * VLD + cq) << 2), Vb + off);
        }
        asm volatile("cp.async.commit_group;\n");
    };

    load_kv(0, 0);
    asm volatile("cp.async.wait_group 0;\n");
    __syncthreads();

    // Q fragments (pre-scaled by 1/sqrt(d))
    const float scale = rsqrtf((float)D_);
    unsigned qf[12][4];
    #pragma unroll
    for (int kk = 0; kk < 12; kk++) {
        qf[kk][0] = __float_as_uint(Qs[(wm+g  )*QLD + kk*8 + tg    ] * scale);
        qf[kk][1] = __float_as_uint(Qs[(wm+g+8)*QLD + kk*8 + tg    ] * scale);
        qf[kk][2] = __float_as_uint(Qs[(wm+g  )*QLD + kk*8 + tg + 4] * scale);
        qf[kk][3] = __float_as_uint(Qs[(wm+g+8)*QLD + kk*8 + tg + 4] * scale);
    }

    float Oacc[12][4] = {};
    float m0 = -1e30f, m1 = -1e30f, l0 = 0.f, l1 = 0.f;

    for (int t = 0; t < nkt; t++) {
        const int buf = t & 1;
        if (t + 1 < nkt) {
            load_kv(t + 1, buf ^ 1);
            asm volatile("cp.async.wait_group 1;\n");
        } else {
            asm volatile("cp.async.wait_group 0;\n");
        }
        __syncthreads();

        const float* Kst = Ks + buf * FK * KLD;
        const float* Vst = Vs + buf * FK * VLD;

        // ---- S = Q @ K^T (scaled) ----
        float sacc[8][4] = {};
        #pragma unroll
        for (int kk = 0; kk < 12; kk++) {
            unsigned bf[8][2];
            #pragma unroll
            for (int ni = 0; ni < 8; ni++) {
                bf[ni][0] = __float_as_uint(Kst[(ni*8+g)*KLD + kk*8 + tg    ]);
                bf[ni][1] = __float_as_uint(Kst[(ni*8+g)*KLD + kk*8 + tg + 4]);
            }
            #pragma unroll
            for (int ni = 0; ni < 8; ni++)
                mma_tf32(sacc[ni], qf[kk], bf[ni]);
        }

        // ---- mask ----
        const int jb = t * FK + 2*tg;
        #pragma unroll
        for (int ni = 0; ni < 8; ni++) {
            const int j = jb + ni*8;
            if (j     >= jl) { sacc[ni][0] = -1e30f; sacc[ni][2] = -1e30f; }
            if (j + 1 >= jl) { sacc[ni][1] = -1e30f; sacc[ni][3] = -1e30f; }
        }

        // ---- online softmax (rows g, g+8) ----
        float mx0 = -1e30f, mx1 = -1e30f;
        #pragma unroll
        for (int ni = 0; ni < 8; ni++) {
            mx0 = fmaxf(mx0, fmaxf(sacc[ni][0], sacc[ni][1]));
            mx1 = fmaxf(mx1, fmaxf(sacc[ni][2], sacc[ni][3]));
        }
        mx0 = fmaxf(mx0, __shfl_xor_sync(0xffffffffu, mx0, 1));
        mx0 = fmaxf(mx0, __shfl_xor_sync(0xffffffffu, mx0, 2));
        mx1 = fmaxf(mx1, __shfl_xor_sync(0xffffffffu, mx1, 1));
        mx1 = fmaxf(mx1, __shfl_xor_sync(0xffffffffu, mx1, 2));
        const float nm0 = fmaxf(m0, mx0), nm1 = fmaxf(m1, mx1);
        const float a0 = __expf(m0 - nm0), a1 = __expf(m1 - nm1);
        float rs0 = 0.f, rs1 = 0.f;
        #pragma unroll
        for (int ni = 0; ni < 8; ni++) {
            sacc[ni][0] = __expf(sacc[ni][0] - nm0);
            sacc[ni][1] = __expf(sacc[ni][1] - nm0);
            sacc[ni][2] = __expf(sacc[ni][2] - nm1);
            sacc[ni][3] = __expf(sacc[ni][3] - nm1);
            rs0 += sacc[ni][0] + sacc[ni][1];
            rs1 += sacc[ni][2] + sacc[ni][3];
        }
        rs0 += __shfl_xor_sync(0xffffffffu, rs0, 1);
        rs0 += __shfl_xor_sync(0xffffffffu, rs0, 2);
        rs1 += __shfl_xor_sync(0xffffffffu, rs1, 1);
        rs1 += __shfl_xor_sync(0xffffffffu, rs1, 2);
        l0 = l0 * a0 + rs0;
        l1 = l1 * a1 + rs1;
        m0 = nm0; m1 = nm1;
        #pragma unroll
        for (int nj = 0; nj < 12; nj++) {
            Oacc[nj][0] *= a0; Oacc[nj][1] *= a0;
            Oacc[nj][2] *= a1; Oacc[nj][3] *= a1;
        }

        // ---- stage P (per-warp-private rows) ----
        #pragma unroll
        for (int ni = 0; ni < 8; ni++) {
            *(float2*)&Ps[(wm+g  )*PLD + ni*8 + 2*tg] = make_float2(sacc[ni][0], sacc[ni][1]);
            *(float2*)&Ps[(wm+g+8)*PLD + ni*8 + 2*tg] = make_float2(sacc[ni][2], sacc[ni][3]);
        }
        __syncwarp();

        // ---- O += P @ V ----
        #pragma unroll
        for (int kk = 0; kk < 8; kk++) {
            unsigned af[4];
            af[0] = __float_as_uint(Ps[(wm+g  )*PLD + kk*8 + tg    ]);
            af[1] = __float_as_uint(Ps[(wm+g+8)*PLD + kk*8 + tg    ]);
            af[2] = __float_as_uint(Ps[(wm+g  )*PLD + kk*8 + tg + 4]);
            af[3] = __float_as_uint(Ps[(wm+g+8)*PLD + kk*8 + tg + 4]);
            #pragma unroll
            for (int nj = 0; nj < 12; nj++) {
                unsigned bv[2];
                bv[0] = __float_as_uint(Vst[(kk*8+tg  )*VLD + nj*8 + g]);
                bv[1] = __float_as_uint(Vst[(kk*8+tg+4)*VLD + nj*8 + g]);
                mma_tf32(Oacc[nj], af, bv);
            }
        }
        __syncthreads();   // protect K/V buffers before next prefetch
    }

    // ---- epilogue ----
    const float inv0 = 1.f / l0, inv1 = 1.f / l1;
    #pragma unroll
    for (int nj = 0; nj < 12; nj++) {
        const int ccol = nj*8 + 2*tg;
        if (i0 + wm + g < el)
            *(float2*)&AOb[(size_t)(wm+g  )*C_ + ccol] =
                make_float2(Oacc[nj][0]*inv0, Oacc[nj][1]*inv0);
        if (i0 + wm + g + 8 < el)
            *(float2*)&AOb[(size_t)(wm+g+8)*C_ + ccol] =
                make_float2(Oacc[nj][2]*inv1, Oacc[nj][3]*inv1);
    }
}

// ---------------- tf32 GEMM, 3-stage cp.async pipeline, ragged block-skip ----------------
#define AS_LD 36
#define BSN_LD 136
#define NSTAGE 3

template <int EPI>
__global__ __launch_bounds__(256, 2)
void mma_gemm(const float* __restrict__ A, const float* __restrict__ Bm,
              const float* __restrict__ bias, const float* __restrict__ R,
              float* __restrict__ Cc,
              int M, int N, int K, int lda, int ldb, int ldc,
              const int* __restrict__ eff, const int* __restrict__ usp,
              int rowsPB, int multMode) {
    const int m0 = blockIdx.y * 128, n0 = blockIdx.x * 128;

    // ragged skip: whole 128-row block beyond this batch's effective length
    if (rowsPB) {
        const int b = m0 / rowsPB;
        const int mult = multMode ? usp[0] : 1;
        if (m0 - b * rowsPB >= eff[b] * mult) return;
    }

    extern __shared__ float smem[];
    constexpr int ASZ = 128 * AS_LD;
    constexpr int BSZ = 32 * BSN_LD;
    float* As = smem;
    float* Bs = smem + NSTAGE * ASZ;
    const uint32_t sa = (uint32_t)__cvta_generic_to_shared(As);
    const uint32_t sb = (uint32_t)__cvta_generic_to_shared(Bs);

    const int tid = threadIdx.x, lane = tid & 31, warp = tid >> 5;
    const int wm = (warp & 1) * 64;
    const int wn = (warp >> 1) * 32;
    const int g = lane >> 2, tg = lane & 3;

    float acc[4][4][4] = {};
    const int nIter = K >> 5;

    auto load_tile = [&](int it, int buf) {
        const int kbase = it * 32;
        #pragma unroll
        for (int i = 0; i < 4; i++) {
            int fid = tid + i * 256;
            int m = fid >> 3, kc = (fid & 7) * 4;
            cpa16(sa + (uint32_t)((buf * ASZ + m * AS_LD + kc) << 2),
                  A + (size_t)(m0 + m) * lda + kbase + kc);
        }
        #pragma unroll
        for (int i = 0; i < 4; i++) {
            int fid = tid + i * 256;
            int k = fid >> 5, nc = (fid & 31) * 4;
            cpa16(sb + (uint32_t)((buf * BSZ + k * BSN_LD + nc) << 2),
                  Bm + (size_t)(kbase + k) * ldb + n0 + nc);
        }
        asm volatile("cp.async.commit_group;\n");
    };

    load_tile(0, 0);
    if (nIter > 1) load_tile(1, 1);

    for (int it = 0; it < nIter; it++) {
        const int buf = it % NSTAGE;
        if (it + 2 < nIter) {
            load_tile(it + 2, (it + 2) % NSTAGE);
            asm volatile("cp.async.wait_group 2;\n");
        } else if (it + 1 < nIter) {
            asm volatile("cp.async.wait_group 1;\n");
        } else {
            asm volatile("cp.async.wait_group 0;\n");
        }
        __syncthreads();

        const float* Asb = As + buf * ASZ;
        const float* Bsb = Bs + buf * BSZ;
        #pragma unroll
        for (int kk = 0; kk < 32; kk += 8) {
            unsigned a[4][4], bfr[4][2];
            #pragma unroll
            for (int mi = 0; mi < 4; mi++) {
                const float* ap = Asb + (wm + mi * 16 + g) * AS_LD + kk + tg;
                a[mi][0] = __float_as_uint(ap[0]);
                a[mi][2] = __float_as_uint(ap[4]);
                a[mi][1] = __float_as_uint(ap[8 * AS_LD]);
                a[mi][3] = __float_as_uint(ap[8 * AS_LD + 4]);
            }
            #pragma unroll
            for (int ni = 0; ni < 4; ni++) {
                bfr[ni][0] = __float_as_uint(Bsb[(kk + tg) * BSN_LD + wn + ni * 8 + g]);
                bfr[ni][1] = __float_as_uint(Bsb[(kk + 4 + tg) * BSN_LD + wn + ni * 8 + g]);
            }
            #pragma unroll
            for (int mi = 0; mi < 4; mi++)
                #pragma unroll
                for (int ni = 0; ni < 4; ni++)
                    mma_tf32(acc[mi][ni], a[mi], bfr[ni]);
        }
        __syncthreads();
    }

    // ---- epilogue (all N multiples of 128: no bounds checks; float2 traffic) ----
    #pragma unroll
    for (int mi = 0; mi < 4; mi++) {
        const int r0 = m0 + wm + mi * 16 + g;
        const int r1 = r0 + 8;
        #pragma unroll
        for (int ni = 0; ni < 4; ni++) {
            const int cc = n0 + wn + ni * 8 + 2 * tg;
            float v00 = acc[mi][ni][0], v01 = acc[mi][ni][1];
            float v10 = acc[mi][ni][2], v11 = acc[mi][ni][3];
            if (EPI >= 2) {
                const float2 bz = *(const float2*)&bias[cc];
                v00 += bz.x; v01 += bz.y; v10 += bz.x; v11 += bz.y;
            }
            if (EPI == 2) {
                v00 = 0.5f * v00 * (1.0f + erff(v00 * 0.70710678118654752f));
                v01 = 0.5f * v01 * (1.0f + erff(v01 * 0.70710678118654752f));
                v10 = 0.5f * v10 * (1.0f + erff(v10 * 0.70710678118654752f));
                v11 = 0.5f * v11 * (1.0f + erff(v11 * 0.70710678118654752f));
            }
            if (EPI == 3) {
                const float2 ra = *(const float2*)&R[(size_t)r0 * ldc + cc];
                const float2 rb = *(const float2*)&R[(size_t)r1 * ldc + cc];
                v00 += ra.x; v01 += ra.y; v10 += rb.x; v11 += rb.y;
            }
            *(float2*)&Cc[(size_t)r0 * ldc + cc] = make_float2(v00, v01);
            *(float2*)&Cc[(size_t)r1 * ldc + cc] = make_float2(v10, v11);
        }
    }
}

// ---------------- host-side launch helpers ----------------
template <int EPI>
static void launch_gemm(const float* A, const float* Bm, const float* bias,
                        const float* R, float* C,
                        int M, int N, int K, int lda, int ldb, int ldc,
                        const int* eff = nullptr, const int* usp = nullptr,
                        int rowsPB = 0, int multMode = 0) {
    constexpr int ASZ = 128 * AS_LD;
    constexpr int BSZ = 32 * BSN_LD;
    const int smemBytes = NSTAGE * (ASZ + BSZ) * 4;
    cudaFuncSetAttribute(mma_gemm<EPI>,
                         cudaFuncAttributeMaxDynamicSharedMemorySize, smemBytes);
    dim3 grid((N + 127) / 128, M / 128, 1), blk(256);
    mma_gemm<EPI><<<grid, blk, smemBytes>>>(A, Bm, bias, R, C, M, N, K, lda, ldb, ldc,
                                            eff, usp, rowsPB, multMode);
}

static void launch_flash(const float* Q, const float* KV, const float* VM, float* AO,
                         const int* eff, const int* usr, int Lk, int self_mode) {
    const int smemBytes = (FQ*QLD + 2*FK*KLD + 2*FK*VLD + FQ*PLD) * 4;
    cudaFuncSetAttribute(flash_kernel,
                         cudaFuncAttributeMaxDynamicSharedMemorySize, smemBytes);
    dim3 grid(L_ / FQ, B_ * H_), blk(256);
    flash_kernel<<<grid, blk, smemBytes>>>(Q, KV, VM, AO, eff, usr, Lk, self_mode);
}

extern "C" void kernel_launch(void* const* d_in, const int* in_sizes, int n_in,
                              void* d_out, int out_size) {
    const float* x    = (const float*)d_in[0];
    const float* c    = (const float*)d_in[1];
    const int*   eff  = (const int*)  d_in[2];
    const int*   usr  = (const int*)  d_in[3];
    const float* Wq1  = (const float*)d_in[4];
    const float* Wkv1 = (const float*)d_in[5];
    const float* Wo1  = (const float*)d_in[6];
    const float* bo1  = (const float*)d_in[7];
    const float* Wq2  = (const float*)d_in[8];
    const float* Wkv2 = (const float*)d_in[9];
    const float* Wo2  = (const float*)d_in[10];
    const float* bo2  = (const float*)d_in[11];
    const float* g1   = (const float*)d_in[12];
    const float* b1   = (const float*)d_in[13];
    const float* g2   = (const float*)d_in[14];
    const float* b2   = (const float*)d_in[15];
    const float* g4   = (const float*)d_in[16];
    const float* b4   = (const float*)d_in[17];
    const float* gc   = (const float*)d_in[18];
    const float* bc   = (const float*)d_in[19];
    const float* Wf1  = (const float*)d_in[20];
    const float* bf1  = (const float*)d_in[21];
    const float* Wf2  = (const float*)d_in[22];
    const float* bf2  = (const float*)d_in[23];
    float* out = (float*)d_out;

    float *XN, *CN, *Q, *KV, *AO, *X2, *Hf, *VM, *RMp;
    cudaGetSymbolAddress((void**)&XN, g_XN);
    cudaGetSymbolAddress((void**)&CN, g_CN);
    cudaGetSymbolAddress((void**)&Q,  g_Q);
    cudaGetSymbolAddress((void**)&KV, g_KV);
    cudaGetSymbolAddress((void**)&AO, g_AO);
    cudaGetSymbolAddress((void**)&X2, g_X2);
    cudaGetSymbolAddress((void**)&Hf, g_H);
    cudaGetSymbolAddress((void**)&VM, g_VM);
    cudaGetSymbolAddress((void**)&RMp, g_RMp);

    // ---------- self-attention ----------
    ln_kernel<<<NTX, 256>>>(x, g1, b1, XN);
    launch_gemm<0>(XN, Wq1,  nullptr, nullptr, Q,  NTX, C_,   C_, C_, C_,   C_,
                   eff, usr, L_, 1);
    launch_gemm<0>(XN, Wkv1, nullptr, nullptr, KV, NTX, 2*C_, C_, C_, 2*C_, 2*C_,
                   eff, usr, L_, 1);
    rowmean1_kernel<<<dim3(B_, RS), C_>>>(XN, RMp, L_);
    rowmean2_matvec_kernel<<<B_, C_>>>(RMp, Wkv1 + C_, VM, L_);
    launch_flash(Q, KV, VM, AO, eff, usr, L_, 1);
    launch_gemm<3>(AO, Wo1, bo1, x, X2, NTX, C_, C_, C_, C_, C_);

    // ---------- cross-attention ----------
    ln_kernel<<<NTX, 256>>>(X2, g2, b2, XN);
    ln_kernel<<<NTC, 256>>>(c,  gc, bc, CN);
    launch_gemm<0>(XN, Wq2,  nullptr, nullptr, Q,  NTX, C_,   C_, C_, C_,   C_,
                   eff, usr, L_, 1);
    launch_gemm<0>(CN, Wkv2, nullptr, nullptr, KV, NTC, 2*C_, C_, C_, 2*C_, 2*C_,
                   eff, usr, S_, 0);
    rowmean1_kernel<<<dim3(B_, RS), C_>>>(CN, RMp, S_);
    rowmean2_matvec_kernel<<<B_, C_>>>(RMp, Wkv2 + C_, VM, S_);
    launch_flash(Q, KV, VM, AO, eff, usr, S_, 0);
    launch_gemm<3>(AO, Wo2, bo2, X2, X2, NTX, C_, C_, C_, C_, C_);

    // ---------- FFN ----------
    ln_kernel<<<NTX, 256>>>(X2, g4, b4, XN);
    launch_gemm<2>(XN, Wf1, bf1, nullptr, Hf, NTX, F_, C_, C_, F_, F_);
    launch_gemm<3>(Hf, Wf2, bf2, X2, out, NTX, C_, F_, F_, C_, C_);
}

// round 10
// speedup vs baseline: 6.8243x; 1.2333x over previous
#include <cuda_runtime.h>
#include <cuda_fp16.h>
#include <math.h>
#include <stdint.h>

#define B_  8
#define L_  1024
#define S_  512
#define C_  768
#define H_  8
#define D_  96
#define F_  3072
#define NTX (B_*L_)
#define NTC (B_*S_)
#define RS 8

// ---------------- scratch ----------------
__device__ __half g_XN[(size_t)NTX*C_ + 64];
__device__ __half g_CN[(size_t)NTC*C_ + 64];
__device__ float  g_Q [(size_t)NTX*C_ + 64];
__device__ float  g_KV[(size_t)NTX*2*C_ + 64];
__device__ __half g_AO[(size_t)NTX*C_ + 64];
__device__ float  g_X2[(size_t)NTX*C_ + 64];
__device__ __half g_Hh[(size_t)NTX*F_ + 64];
__device__ float  g_VM[(size_t)B_*C_ + 64];
__device__ float  g_RMp[(size_t)B_*RS*C_ + 64];
__device__ __half g_WTh[(size_t)9437184 + 64];  // transposed fp16 weights

#define WT_Q1   0
#define WT_KV1  589824
#define WT_O1   1769472
#define WT_Q2   2359296
#define WT_KV2  2949120
#define WT_O2   4128768
#define WT_F1   4718592
#define WT_F2   7077888

// ---------------- reductions ----------------
__device__ __forceinline__ float blockReduceSum(float v) {
    __shared__ float sh[32];
    __syncthreads();
    int lane = threadIdx.x & 31, wid = threadIdx.x >> 5;
    #pragma unroll
    for (int o = 16; o; o >>= 1) v += __shfl_down_sync(0xffffffffu, v, o);
    if (lane == 0) sh[wid] = v;
    __syncthreads();
    int nw = blockDim.x >> 5;
    v = (threadIdx.x < nw) ? sh[threadIdx.x] : 0.0f;
    if (wid == 0) {
        #pragma unroll
        for (int o = 16; o; o >>= 1) v += __shfl_down_sync(0xffffffffu, v, o);
        if (lane == 0) sh[0] = v;
    }
    __syncthreads();
    return sh[0];
}

// ---------------- layernorm -> fp16 output ----------------
__global__ void ln_kernel(const float* __restrict__ X,
                          const float* __restrict__ g, const float* __restrict__ b,
                          __half* __restrict__ Y) {
    const int row = blockIdx.x, tid = threadIdx.x;
    const float4* x4 = (const float4*)(X + (size_t)row * C_);
    float4 v = make_float4(0.f, 0.f, 0.f, 0.f);
    float s = 0.f, s2 = 0.f;
    if (tid < 192) {
        v = x4[tid];
        s  = v.x + v.y + v.z + v.w;
        s2 = v.x*v.x + v.y*v.y + v.z*v.z + v.w*v.w;
    }
    s  = blockReduceSum(s);
    s2 = blockReduceSum(s2);
    const float mean = s * (1.0f / C_);
    const float var  = s2 * (1.0f / C_) - mean * mean;
    const float inv  = rsqrtf(var + 1e-5f);
    if (tid < 192) {
        const float4 gv = ((const float4*)g)[tid];
        const float4 bv = ((const float4*)b)[tid];
        __half2* yp = (__half2*)(Y + (size_t)row * C_ + tid * 4);
        yp[0] = __floats2half2_rn((v.x - mean) * inv * gv.x + bv.x,
                                  (v.y - mean) * inv * gv.y + bv.y);
        yp[1] = __floats2half2_rn((v.z - mean) * inv * gv.z + bv.z,
                                  (v.w - mean) * inv * gv.w + bv.w);
    }
}

// ---------------- weight transpose + fp16 convert: W[K,N] -> WTh[N,K] ----------------
__global__ void transcvt_kernel(const float* __restrict__ W, __half* __restrict__ WTh,
                                int K, int N) {
    __shared__ float t[32][33];
    const int n0 = blockIdx.x * 32, k0 = blockIdx.y * 32;
    const int tx = threadIdx.x, ty = threadIdx.y;
    #pragma unroll
    for (int i = 0; i < 32; i += 8)
        t[ty + i][tx] = W[(size_t)(k0 + ty + i) * N + n0 + tx];
    __syncthreads();
    #pragma unroll
    for (int i = 0; i < 32; i += 8)
        WTh[(size_t)(n0 + ty + i) * K + k0 + tx] = __float2half(t[tx][ty + i]);
}

// ---------------- cp.async / mma helpers ----------------
__device__ __forceinline__ void cpa16(uint32_t dst, const void* src) {
    asm volatile("cp.async.cg.shared.global [%0], [%1], 16;\n" :: "r"(dst), "l"(src));
}

__device__ __forceinline__ void mma_tf32(float* d, const unsigned* a, const unsigned* b) {
    asm volatile(
        "mma.sync.aligned.m16n8k8.row.col.f32.tf32.tf32.f32 "
        "{%0,%1,%2,%3}, {%4,%5,%6,%7}, {%8,%9}, {%0,%1,%2,%3};"
        : "+f"(d[0]), "+f"(d[1]), "+f"(d[2]), "+f"(d[3])
        : "r"(a[0]), "r"(a[1]), "r"(a[2]), "r"(a[3]), "r"(b[0]), "r"(b[1]));
}

__device__ __forceinline__ void mma_f16(float* d, const unsigned* a, const unsigned* b) {
    asm volatile(
        "mma.sync.aligned.m16n8k16.row.col.f32.f16.f16.f32 "
        "{%0,%1,%2,%3}, {%4,%5,%6,%7}, {%8,%9}, {%0,%1,%2,%3};"
        : "+f"(d[0]), "+f"(d[1]), "+f"(d[2]), "+f"(d[3])
        : "r"(a[0]), "r"(a[1]), "r"(a[2]), "r"(a[3]), "r"(b[0]), "r"(b[1]));
}

// ---------------- V-mean via rowmean(XN/CN) @ Wv (fp32 matvec) ----------------
__global__ void rowmean1_kernel(const __half* __restrict__ X, float* __restrict__ part, int Lk) {
    const int b = blockIdx.x, s = blockIdx.y, col = threadIdx.x;
    const int rows = Lk / RS;
    const __half* Xb = X + ((size_t)b * Lk + (size_t)s * rows) * C_ + col;
    float sum = 0.f;
    #pragma unroll 4
    for (int j = 0; j < rows; j++) sum += __half2float(Xb[(size_t)j * C_]);
    part[((size_t)b * RS + s) * C_ + col] = sum;
}
__global__ void rowmean2_matvec_kernel(const float* __restrict__ part,
                                       const float* __restrict__ Wv,
                                       float* __restrict__ VM, int Lk) {
    __shared__ float xm[C_];
    const int b = blockIdx.x, n = threadIdx.x;
    float s = 0.f;
    #pragma unroll
    for (int i = 0; i < RS; i++) s += part[((size_t)b * RS + i) * C_ + n];
    xm[n] = s / (float)Lk;
    __syncthreads();
    float acc = 0.f;
    #pragma unroll 8
    for (int k = 0; k < C_; k++) acc = fmaf(xm[k], Wv[(size_t)k * (2*C_) + n], acc);
    VM[(size_t)b * C_ + n] = acc;
}

// ---------------- flash attention (tf32, fp32 Q/KV in, fp16 AO out) ----------------
#define FQ 128
#define FK 64
#define QLD 100
#define KLD 100
#define VLD 104
#define PLD 68

__global__ __launch_bounds__(256)
void flash_kernel(const float* __restrict__ Qg, const float* __restrict__ KVg,
                  const float* __restrict__ VM, __half* __restrict__ AO,
                  const int* __restrict__ eff, const int* __restrict__ usp,
                  int Lk, int self_mode) {
    extern __shared__ float sm[];
    float* Qs = sm;
    float* Ks = Qs + FQ*QLD;
    float* Vs = Ks + 2*FK*KLD;
    float* Ps = Vs + 2*FK*VLD;

    const int bh = blockIdx.y, b = bh >> 3, h = bh & 7;
    const int i0 = blockIdx.x * FQ;
    const int e  = eff[b];
    const int el = e * usp[0];
    const int jl = self_mode ? el : e;

    const int tid = threadIdx.x, lane = tid & 31, warp = tid >> 5;
    const int g = lane >> 2, tg = lane & 3;
    const int wm = warp * 16;

    const float* Qrow = Qg + ((size_t)b * L_ + i0) * C_ + h * D_;
    const float* Kb   = KVg + (size_t)b * Lk * (2*C_) + h * D_;
    const float* Vb   = Kb + C_;
    __half*      AOb  = AO + ((size_t)b * L_ + i0) * C_ + h * D_;

    const int rm0 = (el > i0) ? ((el - i0 < FQ) ? (el - i0) : FQ) : 0;
    if (rm0 < FQ) {
        const float* vm = VM + (size_t)b * C_ + h * D_;
        for (int idx = tid; idx < (FQ - rm0) * D_; idx += 256) {
            int r = rm0 + idx / D_, cc = idx % D_;
            AOb[(size_t)r * C_ + cc] = __float2half(vm[cc]);
        }
    }
    if (rm0 == 0) return;

    {
        const uint32_t sq = (uint32_t)__cvta_generic_to_shared(Qs);
        for (int t = tid; t < FQ * 24; t += 256) {
            int r = t / 24, cq = (t % 24) * 4;
            cpa16(sq + (uint32_t)((r * QLD + cq) << 2), Qrow + (size_t)r * C_ + cq);
        }
        asm volatile("cp.async.commit_group;\n");
    }

    const uint32_t sk = (uint32_t)__cvta_generic_to_shared(Ks);
    const uint32_t sv = (uint32_t)__cvta_generic_to_shared(Vs);
    const int nkt = (jl + FK - 1) / FK;

    auto load_kv = [&](int t, int buf) {
        const int j0 = t * FK;
        for (int i = tid; i < FK * 24; i += 256) {
            int r = i / 24, cq = (i % 24) * 4;
            const size_t off = (size_t)(j0 + r) * (2*C_) + cq;
            cpa16(sk + (uint32_t)((buf * FK * KLD + r * KLD + cq) << 2), Kb + off);
            cpa16(sv + (uint32_t)((buf * FK * VLD + r * VLD + cq) << 2), Vb + off);
        }
        asm volatile("cp.async.commit_group;\n");
    };

    load_kv(0, 0);
    asm volatile("cp.async.wait_group 0;\n");
    __syncthreads();

    const float scale = rsqrtf((float)D_);
    unsigned qf[12][4];
    #pragma unroll
    for (int kk = 0; kk < 12; kk++) {
        qf[kk][0] = __float_as_uint(Qs[(wm+g  )*QLD + kk*8 + tg    ] * scale);
        qf[kk][1] = __float_as_uint(Qs[(wm+g+8)*QLD + kk*8 + tg    ] * scale);
        qf[kk][2] = __float_as_uint(Qs[(wm+g  )*QLD + kk*8 + tg + 4] * scale);
        qf[kk][3] = __float_as_uint(Qs[(wm+g+8)*QLD + kk*8 + tg + 4] * scale);
    }

    float Oacc[12][4] = {};
    float m0 = -1e30f, m1 = -1e30f, l0 = 0.f, l1 = 0.f;

    for (int t = 0; t < nkt; t++) {
        const int buf = t & 1;
        if (t + 1 < nkt) {
            load_kv(t + 1, buf ^ 1);
            asm volatile("cp.async.wait_group 1;\n");
        } else {
            asm volatile("cp.async.wait_group 0;\n");
        }
        __syncthreads();

        const float* Kst = Ks + buf * FK * KLD;
        const float* Vst = Vs + buf * FK * VLD;

        float sacc[8][4] = {};
        #pragma unroll
        for (int kk = 0; kk < 12; kk++) {
            unsigned bf[8][2];
            #pragma unroll
            for (int ni = 0; ni < 8; ni++) {
                bf[ni][0] = __float_as_uint(Kst[(ni*8+g)*KLD + kk*8 + tg    ]);
                bf[ni][1] = __float_as_uint(Kst[(ni*8+g)*KLD + kk*8 + tg + 4]);
            }
            #pragma unroll
            for (int ni = 0; ni < 8; ni++)
                mma_tf32(sacc[ni], qf[kk], bf[ni]);
        }

        const int jb = t * FK + 2*tg;
        #pragma unroll
        for (int ni = 0; ni < 8; ni++) {
            const int j = jb + ni*8;
            if (j     >= jl) { sacc[ni][0] = -1e30f; sacc[ni][2] = -1e30f; }
            if (j + 1 >= jl) { sacc[ni][1] = -1e30f; sacc[ni][3] = -1e30f; }
        }

        float mx0 = -1e30f, mx1 = -1e30f;
        #pragma unroll
        for (int ni = 0; ni < 8; ni++) {
            mx0 = fmaxf(mx0, fmaxf(sacc[ni][0], sacc[ni][1]));
            mx1 = fmaxf(mx1, fmaxf(sacc[ni][2], sacc[ni][3]));
        }
        mx0 = fmaxf(mx0, __shfl_xor_sync(0xffffffffu, mx0, 1));
        mx0 = fmaxf(mx0, __shfl_xor_sync(0xffffffffu, mx0, 2));
        mx1 = fmaxf(mx1, __shfl_xor_sync(0xffffffffu, mx1, 1));
        mx1 = fmaxf(mx1, __shfl_xor_sync(0xffffffffu, mx1, 2));
        const float nm0 = fmaxf(m0, mx0), nm1 = fmaxf(m1, mx1);
        const float a0 = __expf(m0 - nm0), a1 = __expf(m1 - nm1);
        float rs0 = 0.f, rs1 = 0.f;
        #pragma unroll
        for (int ni = 0; ni < 8; ni++) {
            sacc[ni][0] = __expf(sacc[ni][0] - nm0);
            sacc[ni][1] = __expf(sacc[ni][1] - nm0);
            sacc[ni][2] = __expf(sacc[ni][2] - nm1);
            sacc[ni][3] = __expf(sacc[ni][3] - nm1);
            rs0 += sacc[ni][0] + sacc[ni][1];
            rs1 += sacc[ni][2] + sacc[ni][3];
        }
        rs0 += __shfl_xor_sync(0xffffffffu, rs0, 1);
        rs0 += __shfl_xor_sync(0xffffffffu, rs0, 2);
        rs1 += __shfl_xor_sync(0xffffffffu, rs1, 1);
        rs1 += __shfl_xor_sync(0xffffffffu, rs1, 2);
        l0 = l0 * a0 + rs0;
        l1 = l1 * a1 + rs1;
        m0 = nm0; m1 = nm1;
        #pragma unroll
        for (int nj = 0; nj < 12; nj++) {
            Oacc[nj][0] *= a0; Oacc[nj][1] *= a0;
            Oacc[nj][2] *= a1; Oacc[nj][3] *= a1;
        }

        #pragma unroll
        for (int ni = 0; ni < 8; ni++) {
            *(float2*)&Ps[(wm+g  )*PLD + ni*8 + 2*tg] = make_float2(sacc[ni][0], sacc[ni][1]);
            *(float2*)&Ps[(wm+g+8)*PLD + ni*8 + 2*tg] = make_float2(sacc[ni][2], sacc[ni][3]);
        }
        __syncwarp();

        #pragma unroll
        for (int kk = 0; kk < 8; kk++) {
            unsigned af[4];
            af[0] = __float_as_uint(Ps[(wm+g  )*PLD + kk*8 + tg    ]);
            af[1] = __float_as_uint(Ps[(wm+g+8)*PLD + kk*8 + tg    ]);
            af[2] = __float_as_uint(Ps[(wm+g  )*PLD + kk*8 + tg + 4]);
            af[3] = __float_as_uint(Ps[(wm+g+8)*PLD + kk*8 + tg + 4]);
            #pragma unroll
            for (int nj = 0; nj < 12; nj++) {
                unsigned bv[2];
                bv[0] = __float_as_uint(Vst[(kk*8+tg  )*VLD + nj*8 + g]);
                bv[1] = __float_as_uint(Vst[(kk*8+tg+4)*VLD + nj*8 + g]);
                mma_tf32(Oacc[nj], af, bv);
            }
        }
        __syncthreads();
    }

    const float inv0 = 1.f / l0, inv1 = 1.f / l1;
    #pragma unroll
    for (int nj = 0; nj < 12; nj++) {
        const int ccol = nj*8 + 2*tg;
        if (i0 + wm + g < el)
            *(__half2*)&AOb[(size_t)(wm+g  )*C_ + ccol] =
                __floats2half2_rn(Oacc[nj][0]*inv0, Oacc[nj][1]*inv0);
        if (i0 + wm + g + 8 < el)
            *(__half2*)&AOb[(size_t)(wm+g+8)*C_ + ccol] =
                __floats2half2_rn(Oacc[nj][2]*inv1, Oacc[nj][3]*inv1);
    }
}

// ---------------- fp16 GEMM: C[M,N] = Ah[M,K] @ WTh[N,K]^T ----------------
// 128x128 tile, 8 warps (64m x 32n), m16n8k16, K-slabs of 32, 3-stage cp.async.
// EPI: 0 store, 2 bias+gelu, 3 bias+residual. OUTH: 1 -> fp16 output.
#define HLD 40                      // halves per smem row (32 + 8 pad)
#define HSTG (128*HLD)              // halves per operand per stage
#define NSTAGE 3
#define HSMEM (NSTAGE * 2 * HSTG * 2)   // bytes

template <int EPI, int OUTH>
__global__ __launch_bounds__(256, 2)
void h_gemm(const __half* __restrict__ Ah, const __half* __restrict__ WTh,
            const float* __restrict__ bias, const float* __restrict__ R,
            void* __restrict__ Cc,
            int M, int N, int K, int lda, int ldc,
            const int* __restrict__ eff, const int* __restrict__ usp,
            int rowsPB, int multMode) {
    const int m0 = blockIdx.y * 128, n0 = blockIdx.x * 128;
    if (rowsPB) {
        const int b = m0 / rowsPB;
        const int mult = multMode ? usp[0] : 1;
        if (m0 - b * rowsPB >= eff[b] * mult) return;
    }

    extern __shared__ __half hsm[];
    __half* As = hsm;
    __half* Bs = hsm + NSTAGE * HSTG;
    const uint32_t sa = (uint32_t)__cvta_generic_to_shared(As);
    const uint32_t sb = (uint32_t)__cvta_generic_to_shared(Bs);

    const int tid = threadIdx.x, lane = tid & 31, warp = tid >> 5;
    const int wm = (warp & 1) * 64;
    const int wn = (warp >> 1) * 32;
    const int g = lane >> 2, tg = lane & 3;

    float acc[4][4][4] = {};
    const int nIter = K >> 5;

    auto load_tile = [&](int it, int buf) {
        const int kb = it * 32;
        #pragma unroll
        for (int i = 0; i < 2; i++) {
            const int c = tid + i * 256;            // 0..511
            const int row = c >> 2, kc = (c & 3) * 8;
            cpa16(sa + (uint32_t)((buf * HSTG + row * HLD + kc) * 2),
                  Ah + (size_t)(m0 + row) * lda + kb + kc);
        }
        #pragma unroll
        for (int i = 0; i < 2; i++) {
            const int c = tid + i * 256;
            const int row = c >> 2, kc = (c & 3) * 8;
            cpa16(sb + (uint32_t)((buf * HSTG + row * HLD + kc) * 2),
                  WTh + (size_t)(n0 + row) * K + kb + kc);
        }
        asm volatile("cp.async.commit_group;\n");
    };

    load_tile(0, 0);
    if (nIter > 1) load_tile(1, 1);

    for (int it = 0; it < nIter; it++) {
        const int buf = it % NSTAGE;
        if (it + 2 < nIter) {
            load_tile(it + 2, (it + 2) % NSTAGE);
            asm volatile("cp.async.wait_group 2;\n");
        } else if (it + 1 < nIter) {
            asm volatile("cp.async.wait_group 1;\n");
        } else {
            asm volatile("cp.async.wait_group 0;\n");
        }
        __syncthreads();

        const __half* Asb = As + buf * HSTG;
        const __half* Bsb = Bs + buf * HSTG;
        #pragma unroll
        for (int kk = 0; kk < 32; kk += 16) {
            unsigned a[4][4], bfr[4][2];
            #pragma unroll
            for (int mi = 0; mi < 4; mi++) {
                const __half* ap = Asb + (wm + mi * 16 + g) * HLD + kk + 2 * tg;
                a[mi][0] = *(const unsigned*)ap;
                a[mi][1] = *(const unsigned*)(ap + 8 * HLD);
                a[mi][2] = *(const unsigned*)(ap + 8);
                a[mi][3] = *(const unsigned*)(ap + 8 * HLD + 8);
            }
            #pragma unroll
            for (int ni = 0; ni < 4; ni++) {
                const __half* bp = Bsb + (wn + ni * 8 + g) * HLD + kk + 2 * tg;
                bfr[ni][0] = *(const unsigned*)bp;
                bfr[ni][1] = *(const unsigned*)(bp + 8);
            }
            #pragma unroll
            for (int mi = 0; mi < 4; mi++)
                #pragma unroll
                for (int ni = 0; ni < 4; ni++)
                    mma_f16(acc[mi][ni], a[mi], bfr[ni]);
        }
        __syncthreads();
    }

    // ---- epilogue ----
    #pragma unroll
    for (int mi = 0; mi < 4; mi++) {
        const int r0 = m0 + wm + mi * 16 + g;
        const int r1 = r0 + 8;
        #pragma unroll
        for (int ni = 0; ni < 4; ni++) {
            const int cc = n0 + wn + ni * 8 + 2 * tg;
            float v00 = acc[mi][ni][0], v01 = acc[mi][ni][1];
            float v10 = acc[mi][ni][2], v11 = acc[mi][ni][3];
            if (EPI >= 2) {
                const float2 bz = *(const float2*)&bias[cc];
                v00 += bz.x; v01 += bz.y; v10 += bz.x; v11 += bz.y;
            }
            if (EPI == 2) {
                v00 = 0.5f * v00 * (1.0f + erff(v00 * 0.70710678118654752f));
                v01 = 0.5f * v01 * (1.0f + erff(v01 * 0.70710678118654752f));
                v10 = 0.5f * v10 * (1.0f + erff(v10 * 0.70710678118654752f));
                v11 = 0.5f * v11 * (1.0f + erff(v11 * 0.70710678118654752f));
            }
            if (EPI == 3) {
                const float2 ra = *(const float2*)&R[(size_t)r0 * ldc + cc];
                const float2 rb = *(const float2*)&R[(size_t)r1 * ldc + cc];
                v00 += ra.x; v01 += ra.y; v10 += rb.x; v11 += rb.y;
            }
            if (OUTH) {
                __half* Ch = (__half*)Cc;
                *(__half2*)&Ch[(size_t)r0 * ldc + cc] = __floats2half2_rn(v00, v01);
                *(__half2*)&Ch[(size_t)r1 * ldc + cc] = __floats2half2_rn(v10, v11);
            } else {
                float* Cf = (float*)Cc;
                *(float2*)&Cf[(size_t)r0 * ldc + cc] = make_float2(v00, v01);
                *(float2*)&Cf[(size_t)r1 * ldc + cc] = make_float2(v10, v11);
            }
        }
    }
}

// ---------------- host-side launch helpers ----------------
template <int EPI, int OUTH>
static void launch_hgemm(const __half* Ah, const __half* WTh, const float* bias,
                         const float* R, void* C,
                         int M, int N, int K, int lda, int ldc,
                         const int* eff = nullptr, const int* usp = nullptr,
                         int rowsPB = 0, int multMode = 0) {
    cudaFuncSetAttribute(h_gemm<EPI, OUTH>,
                         cudaFuncAttributeMaxDynamicSharedMemorySize, HSMEM);
    dim3 grid(N / 128, M / 128, 1), blk(256);
    h_gemm<EPI, OUTH><<<grid, blk, HSMEM>>>(Ah, WTh, bias, R, C, M, N, K, lda, ldc,
                                            eff, usp, rowsPB, multMode);
}

static void launch_flash(const float* Q, const float* KV, const float* VM, __half* AO,
                         const int* eff, const int* usr, int Lk, int self_mode) {
    const int smemBytes = (FQ*QLD + 2*FK*KLD + 2*FK*VLD + FQ*PLD) * 4;
    cudaFuncSetAttribute(flash_kernel,
                         cudaFuncAttributeMaxDynamicSharedMemorySize, smemBytes);
    dim3 grid(L_ / FQ, B_ * H_), blk(256);
    flash_kernel<<<grid, blk, smemBytes>>>(Q, KV, VM, AO, eff, usr, Lk, self_mode);
}

static void launch_transcvt(const float* W, __half* WTh, int K, int N) {
    transcvt_kernel<<<dim3(N / 32, K / 32), dim3(32, 8)>>>(W, WTh, K, N);
}

extern "C" void kernel_launch(void* const* d_in, const int* in_sizes, int n_in,
                              void* d_out, int out_size) {
    const float* x    = (const float*)d_in[0];
    const float* c    = (const float*)d_in[1];
    const int*   eff  = (const int*)  d_in[2];
    const int*   usr  = (const int*)  d_in[3];
    const float* Wq1  = (const float*)d_in[4];
    const float* Wkv1 = (const float*)d_in[5];
    const float* Wo1  = (const float*)d_in[6];
    const float* bo1  = (const float*)d_in[7];
    const float* Wq2  = (const float*)d_in[8];
    const float* Wkv2 = (const float*)d_in[9];
    const float* Wo2  = (const float*)d_in[10];
    const float* bo2  = (const float*)d_in[11];
    const float* g1   = (const float*)d_in[12];
    const float* b1   = (const float*)d_in[13];
    const float* g2   = (const float*)d_in[14];
    const float* b2   = (const float*)d_in[15];
    const float* g4   = (const float*)d_in[16];
    const float* b4   = (const float*)d_in[17];
    const float* gc   = (const float*)d_in[18];
    const float* bc   = (const float*)d_in[19];
    const float* Wf1  = (const float*)d_in[20];
    const float* bf1  = (const float*)d_in[21];
    const float* Wf2  = (const float*)d_in[22];
    const float* bf2  = (const float*)d_in[23];
    float* out = (float*)d_out;

    __half *XN, *CN, *AO, *Hf, *WT;
    float *Q, *KV, *X2, *VM, *RMp;
    cudaGetSymbolAddress((void**)&XN, g_XN);
    cudaGetSymbolAddress((void**)&CN, g_CN);
    cudaGetSymbolAddress((void**)&Q,  g_Q);
    cudaGetSymbolAddress((void**)&KV, g_KV);
    cudaGetSymbolAddress((void**)&AO, g_AO);
    cudaGetSymbolAddress((void**)&X2, g_X2);
    cudaGetSymbolAddress((void**)&Hf, g_Hh);
    cudaGetSymbolAddress((void**)&VM, g_VM);
    cudaGetSymbolAddress((void**)&RMp, g_RMp);
    cudaGetSymbolAddress((void**)&WT, g_WTh);

    // ---------- weight transpose + fp16 convert ----------
    launch_transcvt(Wq1,  WT + WT_Q1,  C_, C_);
    launch_transcvt(Wkv1, WT + WT_KV1, C_, 2*C_);
    launch_transcvt(Wo1,  WT + WT_O1,  C_, C_);
    launch_transcvt(Wq2,  WT + WT_Q2,  C_, C_);
    launch_transcvt(Wkv2, WT + WT_KV2, C_, 2*C_);
    launch_transcvt(Wo2,  WT + WT_O2,  C_, C_);
    launch_transcvt(Wf1,  WT + WT_F1,  C_, F_);
    launch_transcvt(Wf2,  WT + WT_F2,  F_, C_);

    // ---------- self-attention ----------
    ln_kernel<<<NTX, 256>>>(x, g1, b1, XN);
    launch_hgemm<0,0>(XN, WT + WT_Q1,  nullptr, nullptr, Q,  NTX, C_,   C_, C_, C_,
                      eff, usr, L_, 1);
    launch_hgemm<0,0>(XN, WT + WT_KV1, nullptr, nullptr, KV, NTX, 2*C_, C_, C_, 2*C_,
                      eff, usr, L_, 1);
    rowmean1_kernel<<<dim3(B_, RS), C_>>>(XN, RMp, L_);
    rowmean2_matvec_kernel<<<B_, C_>>>(RMp, Wkv1 + C_, VM, L_);
    launch_flash(Q, KV, VM, AO, eff, usr, L_, 1);
    launch_hgemm<3,0>(AO, WT + WT_O1, bo1, x, X2, NTX, C_, C_, C_, C_);

    // ---------- cross-attention ----------
    ln_kernel<<<NTX, 256>>>(X2, g2, b2, XN);
    ln_kernel<<<NTC, 256>>>(c,  gc, bc, CN);
    launch_hgemm<0,0>(XN, WT + WT_Q2,  nullptr, nullptr, Q,  NTX, C_,   C_, C_, C_,
                      eff, usr, L_, 1);
    launch_hgemm<0,0>(CN, WT + WT_KV2, nullptr, nullptr, KV, NTC, 2*C_, C_, C_, 2*C_,
                      eff, usr, S_, 0);
    rowmean1_kernel<<<dim3(B_, RS), C_>>>(CN, RMp, S_);
    rowmean2_matvec_kernel<<<B_, C_>>>(RMp, Wkv2 + C_, VM, S_);
    launch_flash(Q, KV, VM, AO, eff, usr, S_, 0);
    launch_hgemm<3,0>(AO, WT + WT_O2, bo2, X2, X2, NTX, C_, C_, C_, C_);

    // ---------- FFN ----------
    ln_kernel<<<NTX, 256>>>(X2, g4, b4, XN);
    launch_hgemm<2,1>(XN, WT + WT_F1, bf1, nullptr, Hf, NTX, F_, C_, C_, F_);
    launch_hgemm<3,0>(Hf, WT + WT_F2, bf2, X2, out, NTX, C_, F_, F_, C_);
}

// round 11
// speedup vs baseline: 7.3036x; 1.0702x over previous
#include <cuda_runtime.h>
#include <cuda_fp16.h>
#include <math.h>
#include <stdint.h>

#define B_  8
#define L_  1024
#define S_  512
#define C_  768
#define H_  8
#define D_  96
#define F_  3072
#define NTX (B_*L_)
#define NTC (B_*S_)
#define RS 8

// ---------------- scratch ----------------
__device__ __half g_XN[(size_t)NTX*C_ + 64];
__device__ __half g_CN[(size_t)NTC*C_ + 64];
__device__ __half g_QKV[(size_t)NTX*3*C_ + 64];
__device__ __half g_Qc [(size_t)NTX*C_ + 64];
__device__ __half g_KVc[(size_t)NTC*2*C_ + 64];
__device__ __half g_AO[(size_t)NTX*C_ + 64];
__device__ float  g_X2[(size_t)NTX*C_ + 64];
__device__ __half g_Hh[(size_t)NTX*F_ + 64];
__device__ float  g_VM[(size_t)B_*C_ + 64];
__device__ float  g_RMp[(size_t)B_*RS*C_ + 64];
__device__ __half g_WTh[(size_t)9437184 + 64];

#define WT_Q1   0
#define WT_KV1  589824
#define WT_O1   1769472
#define WT_Q2   2359296
#define WT_KV2  2949120
#define WT_O2   4128768
#define WT_F1   4718592
#define WT_F2   7077888

// ---------------- reductions ----------------
__device__ __forceinline__ float blockReduceSum(float v) {
    __shared__ float sh[32];
    __syncthreads();
    int lane = threadIdx.x & 31, wid = threadIdx.x >> 5;
    #pragma unroll
    for (int o = 16; o; o >>= 1) v += __shfl_down_sync(0xffffffffu, v, o);
    if (lane == 0) sh[wid] = v;
    __syncthreads();
    int nw = blockDim.x >> 5;
    v = (threadIdx.x < nw) ? sh[threadIdx.x] : 0.0f;
    if (wid == 0) {
        #pragma unroll
        for (int o = 16; o; o >>= 1) v += __shfl_down_sync(0xffffffffu, v, o);
        if (lane == 0) sh[0] = v;
    }
    __syncthreads();
    return sh[0];
}

// ---------------- layernorm -> fp16 ----------------
__global__ void ln_kernel(const float* __restrict__ X,
                          const float* __restrict__ g, const float* __restrict__ b,
                          __half* __restrict__ Y) {
    const int row = blockIdx.x, tid = threadIdx.x;
    const float4* x4 = (const float4*)(X + (size_t)row * C_);
    float4 v = make_float4(0.f, 0.f, 0.f, 0.f);
    float s = 0.f, s2 = 0.f;
    if (tid < 192) {
        v = x4[tid];
        s  = v.x + v.y + v.z + v.w;
        s2 = v.x*v.x + v.y*v.y + v.z*v.z + v.w*v.w;
    }
    s  = blockReduceSum(s);
    s2 = blockReduceSum(s2);
    const float mean = s * (1.0f / C_);
    const float var  = s2 * (1.0f / C_) - mean * mean;
    const float inv  = rsqrtf(var + 1e-5f);
    if (tid < 192) {
        const float4 gv = ((const float4*)g)[tid];
        const float4 bv = ((const float4*)b)[tid];
        __half2* yp = (__half2*)(Y + (size_t)row * C_ + tid * 4);
        yp[0] = __floats2half2_rn((v.x - mean) * inv * gv.x + bv.x,
                                  (v.y - mean) * inv * gv.y + bv.y);
        yp[1] = __floats2half2_rn((v.z - mean) * inv * gv.z + bv.z,
                                  (v.w - mean) * inv * gv.w + bv.w);
    }
}

// ---------------- weight transpose + fp16 ----------------
__global__ void transcvt_kernel(const float* __restrict__ W, __half* __restrict__ WTh,
                                int K, int N) {
    __shared__ float t[32][33];
    const int n0 = blockIdx.x * 32, k0 = blockIdx.y * 32;
    const int tx = threadIdx.x, ty = threadIdx.y;
    #pragma unroll
    for (int i = 0; i < 32; i += 8)
        t[ty + i][tx] = W[(size_t)(k0 + ty + i) * N + n0 + tx];
    __syncthreads();
    #pragma unroll
    for (int i = 0; i < 32; i += 8)
        WTh[(size_t)(n0 + ty + i) * K + k0 + tx] = __float2half(t[tx][ty + i]);
}

// ---------------- asm helpers ----------------
__device__ __forceinline__ void cpa16(uint32_t dst, const void* src) {
    asm volatile("cp.async.cg.shared.global [%0], [%1], 16;\n" :: "r"(dst), "l"(src));
}

__device__ __forceinline__ void mma_f16(float* d, const unsigned* a, const unsigned* b) {
    asm volatile(
        "mma.sync.aligned.m16n8k16.row.col.f32.f16.f16.f32 "
        "{%0,%1,%2,%3}, {%4,%5,%6,%7}, {%8,%9}, {%0,%1,%2,%3};"
        : "+f"(d[0]), "+f"(d[1]), "+f"(d[2]), "+f"(d[3])
        : "r"(a[0]), "r"(a[1]), "r"(a[2]), "r"(a[3]), "r"(b[0]), "r"(b[1]));
}

__device__ __forceinline__ void ldmx4t(unsigned* r, uint32_t addr) {
    asm volatile("ldmatrix.sync.aligned.m8n8.x4.trans.shared.b16 {%0,%1,%2,%3}, [%4];"
                 : "=r"(r[0]), "=r"(r[1]), "=r"(r[2]), "=r"(r[3]) : "r"(addr));
}

// ---------------- V-mean via rowmean @ Wv ----------------
__global__ void rowmean1_kernel(const __half* __restrict__ X, float* __restrict__ part, int Lk) {
    const int b = blockIdx.x, s = blockIdx.y, col = threadIdx.x;
    const int rows = Lk / RS;
    const __half* Xb = X + ((size_t)b * Lk + (size_t)s * rows) * C_ + col;
    float sum = 0.f;
    #pragma unroll 4
    for (int j = 0; j < rows; j++) sum += __half2float(Xb[(size_t)j * C_]);
    part[((size_t)b * RS + s) * C_ + col] = sum;
}
__global__ void rowmean2_matvec_kernel(const float* __restrict__ part,
                                       const float* __restrict__ Wv,
                                       float* __restrict__ VM, int Lk) {
    __shared__ float xm[C_];
    const int b = blockIdx.x, n = threadIdx.x;
    float s = 0.f;
    #pragma unroll
    for (int i = 0; i < RS; i++) s += part[((size_t)b * RS + i) * C_ + n];
    xm[n] = s / (float)Lk;
    __syncthreads();
    float acc = 0.f;
    #pragma unroll 8
    for (int k = 0; k < C_; k++) acc = fmaf(xm[k], Wv[(size_t)k * (2*C_) + n], acc);
    VM[(size_t)b * C_ + n] = acc;
}

// ---------------- fp16 flash attention ----------------
#define FQ 128
#define FK 64
#define QLH 104
#define KLH 104
#define VLH 104
#define PLH 72

__global__ __launch_bounds__(256, 2)
void flash_kernel(const __half* __restrict__ Qg, int qStride,
                  const __half* __restrict__ Kg, const __half* __restrict__ Vg, int kvStride,
                  const float* __restrict__ VM, __half* __restrict__ AO,
                  const int* __restrict__ eff, const int* __restrict__ usp,
                  int Lk, int self_mode) {
    extern __shared__ __half hsm[];
    __half* Qs = hsm;                     // FQ x QLH
    __half* Ks = Qs + FQ*QLH;             // 2 x FK x KLH
    __half* Vs = Ks + 2*FK*KLH;           // 2 x FK x VLH
    __half* Ps = Vs + 2*FK*VLH;           // FQ x PLH

    const int bh = blockIdx.y, b = bh >> 3, h = bh & 7;
    const int i0 = blockIdx.x * FQ;
    const int e  = eff[b];
    const int el = e * usp[0];
    const int jl = self_mode ? el : e;

    const int tid = threadIdx.x, lane = tid & 31, warp = tid >> 5;
    const int g = lane >> 2, tg = lane & 3;
    const int wm = warp * 16;

    const __half* Qrow = Qg + ((size_t)b * L_ + i0) * qStride + h * D_;
    const __half* Kb   = Kg + (size_t)b * Lk * kvStride + h * D_;
    const __half* Vb   = Vg + (size_t)b * Lk * kvStride + h * D_;
    __half*       AOb  = AO + ((size_t)b * L_ + i0) * C_ + h * D_;

    const int rm0 = (el > i0) ? ((el - i0 < FQ) ? (el - i0) : FQ) : 0;
    if (rm0 < FQ) {
        const float* vm = VM + (size_t)b * C_ + h * D_;
        for (int idx = tid; idx < (FQ - rm0) * D_; idx += 256) {
            int r = rm0 + idx / D_, cc = idx % D_;
            AOb[(size_t)r * C_ + cc] = __float2half(vm[cc]);
        }
    }
    if (rm0 == 0) return;

    // Q tile: 128 rows x 96 halves (12 segs of 8)
    {
        const uint32_t sq = (uint32_t)__cvta_generic_to_shared(Qs);
        #pragma unroll
        for (int i = 0; i < 6; i++) {
            int t = tid + i * 256;
            int r = t / 12, sg = (t % 12) * 8;
            cpa16(sq + (uint32_t)((r * QLH + sg) * 2), Qrow + (size_t)r * qStride + sg);
        }
        asm volatile("cp.async.commit_group;\n");
    }

    const uint32_t sk = (uint32_t)__cvta_generic_to_shared(Ks);
    const uint32_t sv = (uint32_t)__cvta_generic_to_shared(Vs);
    const int nkt = (jl + FK - 1) / FK;

    auto load_kv = [&](int t, int buf) {
        const int j0 = t * FK;
        #pragma unroll
        for (int i = 0; i < 3; i++) {
            int c = tid + i * 256;
            int r = c / 12, sg = (c % 12) * 8;
            const size_t off = (size_t)(j0 + r) * kvStride + sg;
            cpa16(sk + (uint32_t)((buf * FK * KLH + r * KLH + sg) * 2), Kb + off);
            cpa16(sv + (uint32_t)((buf * FK * VLH + r * VLH + sg) * 2), Vb + off);
        }
        asm volatile("cp.async.commit_group;\n");
    };

    load_kv(0, 0);
    asm volatile("cp.async.wait_group 0;\n");
    __syncthreads();

    // Q fragments (raw fp16; scale applied post-mma)
    const float scale = rsqrtf((float)D_);
    unsigned qf[6][4];
    #pragma unroll
    for (int kk = 0; kk < 6; kk++) {
        const __half* ap = Qs + (wm + g) * QLH + kk * 16 + 2 * tg;
        qf[kk][0] = *(const unsigned*)ap;
        qf[kk][1] = *(const unsigned*)(ap + 8 * QLH);
        qf[kk][2] = *(const unsigned*)(ap + 8);
        qf[kk][3] = *(const unsigned*)(ap + 8 * QLH + 8);
    }

    float Oacc[12][4] = {};
    float m0 = -1e30f, m1 = -1e30f, l0 = 0.f, l1 = 0.f;

    for (int t = 0; t < nkt; t++) {
        const int buf = t & 1;
        if (t + 1 < nkt) {
            load_kv(t + 1, buf ^ 1);
            asm volatile("cp.async.wait_group 1;\n");
        } else {
            asm volatile("cp.async.wait_group 0;\n");
        }
        __syncthreads();

        const __half* Kst = Ks + buf * FK * KLH;
        const uint32_t svst = sv + (uint32_t)(buf * FK * VLH * 2);

        // ---- S = Q @ K^T ----
        float sacc[8][4] = {};
        #pragma unroll
        for (int kk = 0; kk < 6; kk++) {
            unsigned bf[8][2];
            #pragma unroll
            for (int ni = 0; ni < 8; ni++) {
                const __half* bp = Kst + (ni * 8 + g) * KLH + kk * 16 + 2 * tg;
                bf[ni][0] = *(const unsigned*)bp;
                bf[ni][1] = *(const unsigned*)(bp + 8);
            }
            #pragma unroll
            for (int ni = 0; ni < 8; ni++)
                mma_f16(sacc[ni], qf[kk], bf[ni]);
        }
        #pragma unroll
        for (int ni = 0; ni < 8; ni++) {
            sacc[ni][0] *= scale; sacc[ni][1] *= scale;
            sacc[ni][2] *= scale; sacc[ni][3] *= scale;
        }

        // ---- mask ----
        const int jb = t * FK + 2 * tg;
        #pragma unroll
        for (int ni = 0; ni < 8; ni++) {
            const int j = jb + ni * 8;
            if (j     >= jl) { sacc[ni][0] = -1e30f; sacc[ni][2] = -1e30f; }
            if (j + 1 >= jl) { sacc[ni][1] = -1e30f; sacc[ni][3] = -1e30f; }
        }

        // ---- online softmax ----
        float mx0 = -1e30f, mx1 = -1e30f;
        #pragma unroll
        for (int ni = 0; ni < 8; ni++) {
            mx0 = fmaxf(mx0, fmaxf(sacc[ni][0], sacc[ni][1]));
            mx1 = fmaxf(mx1, fmaxf(sacc[ni][2], sacc[ni][3]));
        }
        mx0 = fmaxf(mx0, __shfl_xor_sync(0xffffffffu, mx0, 1));
        mx0 = fmaxf(mx0, __shfl_xor_sync(0xffffffffu, mx0, 2));
        mx1 = fmaxf(mx1, __shfl_xor_sync(0xffffffffu, mx1, 1));
        mx1 = fmaxf(mx1, __shfl_xor_sync(0xffffffffu, mx1, 2));
        const float nm0 = fmaxf(m0, mx0), nm1 = fmaxf(m1, mx1);
        const float a0 = __expf(m0 - nm0), a1 = __expf(m1 - nm1);
        float rs0 = 0.f, rs1 = 0.f;
        #pragma unroll
        for (int ni = 0; ni < 8; ni++) {
            sacc[ni][0] = __expf(sacc[ni][0] - nm0);
            sacc[ni][1] = __expf(sacc[ni][1] - nm0);
            sacc[ni][2] = __expf(sacc[ni][2] - nm1);
            sacc[ni][3] = __expf(sacc[ni][3] - nm1);
            rs0 += sacc[ni][0] + sacc[ni][1];
            rs1 += sacc[ni][2] + sacc[ni][3];
        }
        rs0 += __shfl_xor_sync(0xffffffffu, rs0, 1);
        rs0 += __shfl_xor_sync(0xffffffffu, rs0, 2);
        rs1 += __shfl_xor_sync(0xffffffffu, rs1, 1);
        rs1 += __shfl_xor_sync(0xffffffffu, rs1, 2);
        l0 = l0 * a0 + rs0;
        l1 = l1 * a1 + rs1;
        m0 = nm0; m1 = nm1;
        #pragma unroll
        for (int nj = 0; nj < 12; nj++) {
            Oacc[nj][0] *= a0; Oacc[nj][1] *= a0;
            Oacc[nj][2] *= a1; Oacc[nj][3] *= a1;
        }

        // ---- stage P fp16 (warp-private rows) ----
        #pragma unroll
        for (int ni = 0; ni < 8; ni++) {
            *(__half2*)&Ps[(wm+g  )*PLH + ni*8 + 2*tg] = __floats2half2_rn(sacc[ni][0], sacc[ni][1]);
            *(__half2*)&Ps[(wm+g+8)*PLH + ni*8 + 2*tg] = __floats2half2_rn(sacc[ni][2], sacc[ni][3]);
        }
        __syncwarp();

        // ---- O += P @ V (V fragments via ldmatrix.trans) ----
        const int vrow = (lane & 7) + (lane & 8);        // k-row within 16-block
        const int vcol = (lane & 16) >> 1;               // +8 n for upper half
        #pragma unroll
        for (int kk = 0; kk < 4; kk++) {
            unsigned af[4];
            const __half* pp = Ps + (wm + g) * PLH + kk * 16 + 2 * tg;
            af[0] = *(const unsigned*)pp;
            af[1] = *(const unsigned*)(pp + 8 * PLH);
            af[2] = *(const unsigned*)(pp + 8);
            af[3] = *(const unsigned*)(pp + 8 * PLH + 8);
            #pragma unroll
            for (int njp = 0; njp < 6; njp++) {
                unsigned vr[4];
                const uint32_t va = svst +
                    (uint32_t)(((kk * 16 + vrow) * VLH + njp * 16 + vcol) * 2);
                ldmx4t(vr, va);
                mma_f16(Oacc[2*njp    ], af, vr);
                mma_f16(Oacc[2*njp + 1], af, vr + 2);
            }
        }
        __syncthreads();
    }

    const float inv0 = 1.f / l0, inv1 = 1.f / l1;
    #pragma unroll
    for (int nj = 0; nj < 12; nj++) {
        const int ccol = nj*8 + 2*tg;
        if (i0 + wm + g < el)
            *(__half2*)&AOb[(size_t)(wm+g  )*C_ + ccol] =
                __floats2half2_rn(Oacc[nj][0]*inv0, Oacc[nj][1]*inv0);
        if (i0 + wm + g + 8 < el)
            *(__half2*)&AOb[(size_t)(wm+g+8)*C_ + ccol] =
                __floats2half2_rn(Oacc[nj][2]*inv1, Oacc[nj][3]*inv1);
    }
}

// ---------------- fp16 GEMM (unchanged from R10) ----------------
#define HLD 40
#define HSTG (128*HLD)
#define NSTAGE 3
#define HSMEM (NSTAGE * 2 * HSTG * 2)

template <int EPI, int OUTH>
__global__ __launch_bounds__(256, 2)
void h_gemm(const __half* __restrict__ Ah, const __half* __restrict__ WTh,
            const float* __restrict__ bias, const float* __restrict__ R,
            void* __restrict__ Cc,
            int M, int N, int K, int lda, int ldc,
            const int* __restrict__ eff, const int* __restrict__ usp,
            int rowsPB, int multMode) {
    const int m0 = blockIdx.y * 128, n0 = blockIdx.x * 128;
    if (rowsPB) {
        const int b = m0 / rowsPB;
        const int mult = multMode ? usp[0] : 1;
        if (m0 - b * rowsPB >= eff[b] * mult) return;
    }

    extern __shared__ __half hsm[];
    __half* As = hsm;
    __half* Bs = hsm + NSTAGE * HSTG;
    const uint32_t sa = (uint32_t)__cvta_generic_to_shared(As);
    const uint32_t sb = (uint32_t)__cvta_generic_to_shared(Bs);

    const int tid = threadIdx.x, lane = tid & 31, warp = tid >> 5;
    const int wm = (warp & 1) * 64;
    const int wn = (warp >> 1) * 32;
    const int g = lane >> 2, tg = lane & 3;

    float acc[4][4][4] = {};
    const int nIter = K >> 5;

    auto load_tile = [&](int it, int buf) {
        const int kb = it * 32;
        #pragma unroll
        for (int i = 0; i < 2; i++) {
            const int c = tid + i * 256;
            const int row = c >> 2, kc = (c & 3) * 8;
            cpa16(sa + (uint32_t)((buf * HSTG + row * HLD + kc) * 2),
                  Ah + (size_t)(m0 + row) * lda + kb + kc);
        }
        #pragma unroll
        for (int i = 0; i < 2; i++) {
            const int c = tid + i * 256;
            const int row = c >> 2, kc = (c & 3) * 8;
            cpa16(sb + (uint32_t)((buf * HSTG + row * HLD + kc) * 2),
                  WTh + (size_t)(n0 + row) * K + kb + kc);
        }
        asm volatile("cp.async.commit_group;\n");
    };

    load_tile(0, 0);
    if (nIter > 1) load_tile(1, 1);

    for (int it = 0; it < nIter; it++) {
        const int buf = it % NSTAGE;
        if (it + 2 < nIter) {
            load_tile(it + 2, (it + 2) % NSTAGE);
            asm volatile("cp.async.wait_group 2;\n");
        } else if (it + 1 < nIter) {
            asm volatile("cp.async.wait_group 1;\n");
        } else {
            asm volatile("cp.async.wait_group 0;\n");
        }
        __syncthreads();

        const __half* Asb = As + buf * HSTG;
        const __half* Bsb = Bs + buf * HSTG;
        #pragma unroll
        for (int kk = 0; kk < 32; kk += 16) {
            unsigned a[4][4], bfr[4][2];
            #pragma unroll
            for (int mi = 0; mi < 4; mi++) {
                const __half* ap = Asb + (wm + mi * 16 + g) * HLD + kk + 2 * tg;
                a[mi][0] = *(const unsigned*)ap;
                a[mi][1] = *(const unsigned*)(ap + 8 * HLD);
                a[mi][2] = *(const unsigned*)(ap + 8);
                a[mi][3] = *(const unsigned*)(ap + 8 * HLD + 8);
            }
            #pragma unroll
            for (int ni = 0; ni < 4; ni++) {
                const __half* bp = Bsb + (wn + ni * 8 + g) * HLD + kk + 2 * tg;
                bfr[ni][0] = *(const unsigned*)bp;
                bfr[ni][1] = *(const unsigned*)(bp + 8);
            }
            #pragma unroll
            for (int mi = 0; mi < 4; mi++)
                #pragma unroll
                for (int ni = 0; ni < 4; ni++)
                    mma_f16(acc[mi][ni], a[mi], bfr[ni]);
        }
        __syncthreads();
    }

    #pragma unroll
    for (int mi = 0; mi < 4; mi++) {
        const int r0 = m0 + wm + mi * 16 + g;
        const int r1 = r0 + 8;
        #pragma unroll
        for (int ni = 0; ni < 4; ni++) {
            const int cc = n0 + wn + ni * 8 + 2 * tg;
            float v00 = acc[mi][ni][0], v01 = acc[mi][ni][1];
            float v10 = acc[mi][ni][2], v11 = acc[mi][ni][3];
            if (EPI >= 2) {
                const float2 bz = *(const float2*)&bias[cc];
                v00 += bz.x; v01 += bz.y; v10 += bz.x; v11 += bz.y;
            }
            if (EPI == 2) {
                v00 = 0.5f * v00 * (1.0f + erff(v00 * 0.70710678118654752f));
                v01 = 0.5f * v01 * (1.0f + erff(v01 * 0.70710678118654752f));
                v10 = 0.5f * v10 * (1.0f + erff(v10 * 0.70710678118654752f));
                v11 = 0.5f * v11 * (1.0f + erff(v11 * 0.70710678118654752f));
            }
            if (EPI == 3) {
                const float2 ra = *(const float2*)&R[(size_t)r0 * ldc + cc];
                const float2 rb = *(const float2*)&R[(size_t)r1 * ldc + cc];
                v00 += ra.x; v01 += ra.y; v10 += rb.x; v11 += rb.y;
            }
            if (OUTH) {
                __half* Ch = (__half*)Cc;
                *(__half2*)&Ch[(size_t)r0 * ldc + cc] = __floats2half2_rn(v00, v01);
                *(__half2*)&Ch[(size_t)r1 * ldc + cc] = __floats2half2_rn(v10, v11);
            } else {
                float* Cf = (float*)Cc;
                *(float2*)&Cf[(size_t)r0 * ldc + cc] = make_float2(v00, v01);
                *(float2*)&Cf[(size_t)r1 * ldc + cc] = make_float2(v10, v11);
            }
        }
    }
}

// ---------------- host helpers ----------------
template <int EPI, int OUTH>
static void launch_hgemm(const __half* Ah, const __half* WTh, const float* bias,
                         const float* R, void* C,
                         int M, int N, int K, int lda, int ldc,
                         const int* eff = nullptr, const int* usp = nullptr,
                         int rowsPB = 0, int multMode = 0) {
    cudaFuncSetAttribute(h_gemm<EPI, OUTH>,
                         cudaFuncAttributeMaxDynamicSharedMemorySize, HSMEM);
    dim3 grid(N / 128, M / 128, 1), blk(256);
    h_gemm<EPI, OUTH><<<grid, blk, HSMEM>>>(Ah, WTh, bias, R, C, M, N, K, lda, ldc,
                                            eff, usp, rowsPB, multMode);
}

static void launch_flash(const __half* Q, int qStride,
                         const __half* Kp, const __half* Vp, int kvStride,
                         const float* VM, __half* AO,
                         const int* eff, const int* usr, int Lk, int self_mode) {
    const int smemBytes = (FQ*QLH + 2*FK*KLH + 2*FK*VLH + FQ*PLH) * 2;
    cudaFuncSetAttribute(flash_kernel,
                         cudaFuncAttributeMaxDynamicSharedMemorySize, smemBytes);
    dim3 grid(L_ / FQ, B_ * H_), blk(256);
    flash_kernel<<<grid, blk, smemBytes>>>(Q, qStride, Kp, Vp, kvStride,
                                           VM, AO, eff, usr, Lk, self_mode);
}

static void launch_transcvt(const float* W, __half* WTh, int K, int N) {
    transcvt_kernel<<<dim3(N / 32, K / 32), dim3(32, 8)>>>(W, WTh, K, N);
}

extern "C" void kernel_launch(void* const* d_in, const int* in_sizes, int n_in,
                              void* d_out, int out_size) {
    const float* x    = (const float*)d_in[0];
    const float* c    = (const float*)d_in[1];
    const int*   eff  = (const int*)  d_in[2];
    const int*   usr  = (const int*)  d_in[3];
    const float* Wq1  = (const float*)d_in[4];
    const float* Wkv1 = (const float*)d_in[5];
    const float* Wo1  = (const float*)d_in[6];
    const float* bo1  = (const float*)d_in[7];
    const float* Wq2  = (const float*)d_in[8];
    const float* Wkv2 = (const float*)d_in[9];
    const float* Wo2  = (const float*)d_in[10];
    const float* bo2  = (const float*)d_in[11];
    const float* g1   = (const float*)d_in[12];
    const float* b1   = (const float*)d_in[13];
    const float* g2   = (const float*)d_in[14];
    const float* b2   = (const float*)d_in[15];
    const float* g4   = (const float*)d_in[16];
    const float* b4   = (const float*)d_in[17];
    const float* gc   = (const float*)d_in[18];
    const float* bc   = (const float*)d_in[19];
    const float* Wf1  = (const float*)d_in[20];
    const float* bf1  = (const float*)d_in[21];
    const float* Wf2  = (const float*)d_in[22];
    const float* bf2  = (const float*)d_in[23];
    float* out = (float*)d_out;

    __half *XN, *CN, *QKV, *Qc, *KVc, *AO, *Hf, *WT;
    float *X2, *VM, *RMp;
    cudaGetSymbolAddress((void**)&XN,  g_XN);
    cudaGetSymbolAddress((void**)&CN,  g_CN);
    cudaGetSymbolAddress((void**)&QKV, g_QKV);
    cudaGetSymbolAddress((void**)&Qc,  g_Qc);
    cudaGetSymbolAddress((void**)&KVc, g_KVc);
    cudaGetSymbolAddress((void**)&AO,  g_AO);
    cudaGetSymbolAddress((void**)&X2,  g_X2);
    cudaGetSymbolAddress((void**)&Hf,  g_Hh);
    cudaGetSymbolAddress((void**)&VM,  g_VM);
    cudaGetSymbolAddress((void**)&RMp, g_RMp);
    cudaGetSymbolAddress((void**)&WT,  g_WTh);

    // ---------- weight transpose + fp16 convert ----------
    launch_transcvt(Wq1,  WT + WT_Q1,  C_, C_);
    launch_transcvt(Wkv1, WT + WT_KV1, C_, 2*C_);
    launch_transcvt(Wo1,  WT + WT_O1,  C_, C_);
    launch_transcvt(Wq2,  WT + WT_Q2,  C_, C_);
    launch_transcvt(Wkv2, WT + WT_KV2, C_, 2*C_);
    launch_transcvt(Wo2,  WT + WT_O2,  C_, C_);
    launch_transcvt(Wf1,  WT + WT_F1,  C_, F_);
    launch_transcvt(Wf2,  WT + WT_F2,  F_, C_);

    // ---------- self-attention (fused QKV projection, N=2304) ----------
    ln_kernel<<<NTX, 256>>>(x, g1, b1, XN);
    launch_hgemm<0,1>(XN, WT + WT_Q1, nullptr, nullptr, QKV, NTX, 3*C_, C_, C_, 3*C_,
                      eff, usr, L_, 1);
    rowmean1_kernel<<<dim3(B_, RS), C_>>>(XN, RMp, L_);
    rowmean2_matvec_kernel<<<B_, C_>>>(RMp, Wkv1 + C_, VM, L_);
    launch_flash(QKV, 3*C_, QKV + C_, QKV + 2*C_, 3*C_, VM, AO, eff, usr, L_, 1);
    launch_hgemm<3,0>(AO, WT + WT_O1, bo1, x, X2, NTX, C_, C_, C_, C_);

    // ---------- cross-attention ----------
    ln_kernel<<<NTX, 256>>>(X2, g2, b2, XN);
    ln_kernel<<<NTC, 256>>>(c,  gc, bc, CN);
    launch_hgemm<0,1>(XN, WT + WT_Q2,  nullptr, nullptr, Qc,  NTX, C_,   C_, C_, C_,
                      eff, usr, L_, 1);
    launch_hgemm<0,1>(CN, WT + WT_KV2, nullptr, nullptr, KVc, NTC, 2*C_, C_, C_, 2*C_,
                      eff, usr, S_, 0);
    rowmean1_kernel<<<dim3(B_, RS), C_>>>(CN, RMp, S_);
    rowmean2_matvec_kernel<<<B_, C_>>>(RMp, Wkv2 + C_, VM, S_);
    launch_flash(Qc, C_, KVc, KVc + C_, 2*C_, VM, AO, eff, usr, S_, 0);
    launch_hgemm<3,0>(AO, WT + WT_O2, bo2, X2, X2, NTX, C_, C_, C_, C_);

    // ---------- FFN ----------
    ln_kernel<<<NTX, 256>>>(X2, g4, b4, XN);
    launch_hgemm<2,1>(XN, WT + WT_F1, bf1, nullptr, Hf, NTX, F_, C_, C_, F_);
    launch_hgemm<3,0>(Hf, WT + WT_F2, bf2, X2, out, NTX, C_, F_, F_, C_);
}